// round 2
// baseline (speedup 1.0000x reference)
#include <cuda_runtime.h>
#include <cuda_bf16.h>
#include <cstdint>
#include <cstddef>

// ============================================================================
// Attention_5480378270188 — bf16x2 (hi/lo split) mma.sync baseline
//   out = softmax(mask(Q Wq^T (K Wk^T)^T)) (V Wv^T)
// B=8, N=M=2048, D_MODEL=D_K=D_V=1024
// 4 stages: proj GEMMs -> score GEMM(+mask) -> softmax -> out GEMM
// All GEMMs use 3-term bf16 split (hi*hi + hi*lo + lo*hi) for ~fp32 accuracy.
// ============================================================================

#define DEV_INLINE __device__ __forceinline__

constexpr int BB = 8;
constexpr int NN = 2048;
constexpr int MM = 2048;
constexpr int DD = 1024;
constexpr float NEG = -1000000000.0f;

constexpr size_t QKV_ELEMS = (size_t)BB * NN * DD;   // 16,777,216
constexpr size_t SCORE_ELEMS = (size_t)BB * NN * MM; // 33,554,432

// Scratch (device globals; no allocation in kernel_launch)
__device__ __nv_bfloat16 g_qhi[QKV_ELEMS];
__device__ __nv_bfloat16 g_qlo[QKV_ELEMS];
__device__ __nv_bfloat16 g_khi[QKV_ELEMS];
__device__ __nv_bfloat16 g_klo[QKV_ELEMS];
__device__ __nv_bfloat16 g_vhi[QKV_ELEMS];
__device__ __nv_bfloat16 g_vlo[QKV_ELEMS];
__device__ float         g_scores[SCORE_ELEMS];
__device__ __nv_bfloat16 g_whi[SCORE_ELEMS];
__device__ __nv_bfloat16 g_wlo[SCORE_ELEMS];

// smem strides (bf16 elements), padded for bank-conflict mitigation
#define LDA  40    // 128 x (32+8)
#define LDBT 136   // 32 x (128+8) for transposed-B (v) tiles

// ---------------------------------------------------------------------------
// PTX helpers
// ---------------------------------------------------------------------------
DEV_INLINE uint32_t smem_u32(const void* p) {
    return (uint32_t)__cvta_generic_to_shared(p);
}

DEV_INLINE void ldsm4(uint32_t r[4], const void* p) {
    uint32_t a = smem_u32(p);
    asm volatile("ldmatrix.sync.aligned.m8n8.x4.shared.b16 {%0,%1,%2,%3}, [%4];\n"
                 : "=r"(r[0]), "=r"(r[1]), "=r"(r[2]), "=r"(r[3]) : "r"(a));
}

DEV_INLINE void ldsm4t(uint32_t r[4], const void* p) {
    uint32_t a = smem_u32(p);
    asm volatile("ldmatrix.sync.aligned.m8n8.x4.trans.shared.b16 {%0,%1,%2,%3}, [%4];\n"
                 : "=r"(r[0]), "=r"(r[1]), "=r"(r[2]), "=r"(r[3]) : "r"(a));
}

DEV_INLINE void mma16816(float c[4], const uint32_t a[4], uint32_t b0, uint32_t b1) {
    asm volatile(
        "mma.sync.aligned.m16n8k16.row.col.f32.bf16.bf16.f32 "
        "{%0,%1,%2,%3},{%4,%5,%6,%7},{%8,%9},{%0,%1,%2,%3};\n"
        : "+f"(c[0]), "+f"(c[1]), "+f"(c[2]), "+f"(c[3])
        : "r"(a[0]), "r"(a[1]), "r"(a[2]), "r"(a[3]), "r"(b0), "r"(b1));
}

DEV_INLINE void split1(float v, __nv_bfloat16& h, __nv_bfloat16& l) {
    h = __float2bfloat16(v);
    l = __float2bfloat16(v - __bfloat162float(h));
}

// split a float4 into hi/lo bf16 pairs, store (o must be 4-elem aligned)
DEV_INLINE void split4_store(float4 v, __nv_bfloat16* ph, __nv_bfloat16* pl, int o) {
    __nv_bfloat16 h0, l0, h1, l1, h2, l2, h3, l3;
    split1(v.x, h0, l0); split1(v.y, h1, l1);
    split1(v.z, h2, l2); split1(v.w, h3, l3);
    *(__nv_bfloat162*)(ph + o)     = __halves2bfloat162(h0, h1);
    *(__nv_bfloat162*)(ph + o + 2) = __halves2bfloat162(h2, h3);
    *(__nv_bfloat162*)(pl + o)     = __halves2bfloat162(l0, l1);
    *(__nv_bfloat162*)(pl + o + 2) = __halves2bfloat162(l2, l3);
}

// ---------------------------------------------------------------------------
// Compute core: one 32-wide K-chunk. CTA tile 128x128, 8 warps (4m x 2n),
// warp tile 32(m) x 64(n). acc[2][8][4] fp32. 3-term bf16x2.
// ---------------------------------------------------------------------------
DEV_INLINE void compute_chunk_nt(const __nv_bfloat16* sAh, const __nv_bfloat16* sAl,
                                 const __nv_bfloat16* sBh, const __nv_bfloat16* sBl,
                                 int wm, int wn, int lane, float (&acc)[2][8][4]) {
#pragma unroll
    for (int kk = 0; kk < 32; kk += 16) {
        uint32_t ah[2][4], al[2][4], bh[4][4], bl[4][4];
#pragma unroll
        for (int mt = 0; mt < 2; mt++) {
            int r = wm + mt * 16 + (lane & 15);
            int c = kk + (lane >> 4) * 8;
            ldsm4(ah[mt], sAh + r * LDA + c);
            ldsm4(al[mt], sAl + r * LDA + c);
        }
#pragma unroll
        for (int p = 0; p < 4; p++) {
            int r = wn + p * 16 + (lane >> 4) * 8 + (lane & 7);
            int c = kk + ((lane >> 3) & 1) * 8;
            ldsm4(bh[p], sBh + r * LDA + c);
            ldsm4(bl[p], sBl + r * LDA + c);
        }
#pragma unroll
        for (int mt = 0; mt < 2; mt++)
#pragma unroll
            for (int p = 0; p < 4; p++) {
                mma16816(acc[mt][2 * p],     ah[mt], bh[p][0], bh[p][1]);
                mma16816(acc[mt][2 * p],     ah[mt], bl[p][0], bl[p][1]);
                mma16816(acc[mt][2 * p],     al[mt], bh[p][0], bh[p][1]);
                mma16816(acc[mt][2 * p + 1], ah[mt], bh[p][2], bh[p][3]);
                mma16816(acc[mt][2 * p + 1], ah[mt], bl[p][2], bl[p][3]);
                mma16816(acc[mt][2 * p + 1], al[mt], bh[p][2], bh[p][3]);
            }
    }
}

// Same, but B stored [k=32][n=128+pad] (row-major K) -> ldmatrix.trans
DEV_INLINE void compute_chunk_t(const __nv_bfloat16* sAh, const __nv_bfloat16* sAl,
                                const __nv_bfloat16* sBh, const __nv_bfloat16* sBl,
                                int wm, int wn, int lane, float (&acc)[2][8][4]) {
#pragma unroll
    for (int kk = 0; kk < 32; kk += 16) {
        uint32_t ah[2][4], al[2][4], bh[4][4], bl[4][4];
#pragma unroll
        for (int mt = 0; mt < 2; mt++) {
            int r = wm + mt * 16 + (lane & 15);
            int c = kk + (lane >> 4) * 8;
            ldsm4(ah[mt], sAh + r * LDA + c);
            ldsm4(al[mt], sAl + r * LDA + c);
        }
#pragma unroll
        for (int p = 0; p < 4; p++) {
            int r = kk + ((lane >> 3) & 1) * 8 + (lane & 7);
            int c = wn + p * 16 + (lane >> 4) * 8;
            ldsm4t(bh[p], sBh + r * LDBT + c);
            ldsm4t(bl[p], sBl + r * LDBT + c);
        }
#pragma unroll
        for (int mt = 0; mt < 2; mt++)
#pragma unroll
            for (int p = 0; p < 4; p++) {
                mma16816(acc[mt][2 * p],     ah[mt], bh[p][0], bh[p][1]);
                mma16816(acc[mt][2 * p],     ah[mt], bl[p][0], bl[p][1]);
                mma16816(acc[mt][2 * p],     al[mt], bh[p][0], bh[p][1]);
                mma16816(acc[mt][2 * p + 1], ah[mt], bh[p][2], bh[p][3]);
                mma16816(acc[mt][2 * p + 1], ah[mt], bl[p][2], bl[p][3]);
                mma16816(acc[mt][2 * p + 1], al[mt], bh[p][2], bh[p][3]);
            }
    }
}

// ---------------------------------------------------------------------------
// Kernel 1: projection  C[r,o] = sum_d X[r,d]*W[o,d] + b[o]
// X: [16384,1024] fp32 (batch fused), W: [1024,1024] fp32. Out: bf16 hi/lo.
// grid (8 colTiles, 128 rowTiles), 256 threads.
// ---------------------------------------------------------------------------
template <int WHICH>
__global__ __launch_bounds__(256, 1) void proj_kernel(const float* __restrict__ X,
                                                      const float* __restrict__ W,
                                                      const float* __restrict__ bias) {
    __shared__ __align__(16) __nv_bfloat16 sAh[128 * LDA], sAl[128 * LDA];
    __shared__ __align__(16) __nv_bfloat16 sBh[128 * LDA], sBl[128 * LDA];
    const int tid = threadIdx.x, lane = tid & 31, warp = tid >> 5;
    const int wm = (warp & 3) * 32, wn = (warp >> 2) * 64;
    const int rowBlk = blockIdx.y * 128, colBlk = blockIdx.x * 128;
    const int lrow = tid >> 1, lcol = (tid & 1) * 16;
    const float* Ag = X + (size_t)(rowBlk + lrow) * DD + lcol;
    const float* Bg = W + (size_t)(colBlk + lrow) * DD + lcol;

    float acc[2][8][4] = {};
    for (int k0 = 0; k0 < DD; k0 += 32) {
        const int o = lrow * LDA + lcol;
#pragma unroll
        for (int i = 0; i < 4; i++) {
            float4 a = *(const float4*)(Ag + k0 + i * 4);
            float4 b = *(const float4*)(Bg + k0 + i * 4);
            split4_store(a, sAh, sAl, o + i * 4);
            split4_store(b, sBh, sBl, o + i * 4);
        }
        __syncthreads();
        compute_chunk_nt(sAh, sAl, sBh, sBl, wm, wn, lane, acc);
        __syncthreads();
    }

    __nv_bfloat16 *Chi, *Clo;
    if (WHICH == 0)      { Chi = g_qhi; Clo = g_qlo; }
    else if (WHICH == 1) { Chi = g_khi; Clo = g_klo; }
    else                 { Chi = g_vhi; Clo = g_vlo; }

#pragma unroll
    for (int mt = 0; mt < 2; mt++)
#pragma unroll
        for (int nt = 0; nt < 8; nt++) {
            int r = rowBlk + wm + mt * 16 + (lane >> 2);
            int c = colBlk + wn + nt * 8 + (lane & 3) * 2;
            float b0 = bias[c], b1 = bias[c + 1];
            {
                __nv_bfloat16 h0, l0, h1, l1;
                split1(acc[mt][nt][0] + b0, h0, l0);
                split1(acc[mt][nt][1] + b1, h1, l1);
                *(__nv_bfloat162*)(Chi + (size_t)r * DD + c) = __halves2bfloat162(h0, h1);
                *(__nv_bfloat162*)(Clo + (size_t)r * DD + c) = __halves2bfloat162(l0, l1);
            }
            {
                __nv_bfloat16 h0, l0, h1, l1;
                split1(acc[mt][nt][2] + b0, h0, l0);
                split1(acc[mt][nt][3] + b1, h1, l1);
                *(__nv_bfloat162*)(Chi + (size_t)(r + 8) * DD + c) = __halves2bfloat162(h0, h1);
                *(__nv_bfloat162*)(Clo + (size_t)(r + 8) * DD + c) = __halves2bfloat162(l0, l1);
            }
        }
}

// ---------------------------------------------------------------------------
// Kernel 2: scores S[b,n,m] = sum_d q[b,n,d]*k[b,m,d], masked.
// grid (16 mTiles, 16 nTiles, 8 batch).
// ---------------------------------------------------------------------------
__global__ __launch_bounds__(256, 1) void score_kernel(const int* __restrict__ mask) {
    __shared__ __align__(16) __nv_bfloat16 sAh[128 * LDA], sAl[128 * LDA];
    __shared__ __align__(16) __nv_bfloat16 sBh[128 * LDA], sBl[128 * LDA];
    const int tid = threadIdx.x, lane = tid & 31, warp = tid >> 5;
    const int wm = (warp & 3) * 32, wn = (warp >> 2) * 64;
    const int b = blockIdx.z;
    const int rowBlk = blockIdx.y * 128, colBlk = blockIdx.x * 128;
    const size_t qoff = (size_t)b * NN * DD;
    const int lrow = tid >> 1, lcol = (tid & 1) * 16;

    const __nv_bfloat16* pqh = g_qhi + qoff + (size_t)(rowBlk + lrow) * DD + lcol;
    const __nv_bfloat16* pql = g_qlo + qoff + (size_t)(rowBlk + lrow) * DD + lcol;
    const __nv_bfloat16* pkh = g_khi + qoff + (size_t)(colBlk + lrow) * DD + lcol;
    const __nv_bfloat16* pkl = g_klo + qoff + (size_t)(colBlk + lrow) * DD + lcol;

    float acc[2][8][4] = {};
    for (int k0 = 0; k0 < DD; k0 += 32) {
        const int o = lrow * LDA + lcol;
        *(uint4*)(sAh + o)     = *(const uint4*)(pqh + k0);
        *(uint4*)(sAh + o + 8) = *(const uint4*)(pqh + k0 + 8);
        *(uint4*)(sAl + o)     = *(const uint4*)(pql + k0);
        *(uint4*)(sAl + o + 8) = *(const uint4*)(pql + k0 + 8);
        *(uint4*)(sBh + o)     = *(const uint4*)(pkh + k0);
        *(uint4*)(sBh + o + 8) = *(const uint4*)(pkh + k0 + 8);
        *(uint4*)(sBl + o)     = *(const uint4*)(pkl + k0);
        *(uint4*)(sBl + o + 8) = *(const uint4*)(pkl + k0 + 8);
        __syncthreads();
        compute_chunk_nt(sAh, sAl, sBh, sBl, wm, wn, lane, acc);
        __syncthreads();
    }

    float* Sg = g_scores + (size_t)b * NN * MM;
#pragma unroll
    for (int mt = 0; mt < 2; mt++)
#pragma unroll
        for (int nt = 0; nt < 8; nt++) {
            int r = rowBlk + wm + mt * 16 + (lane >> 2);
            int c = colBlk + wn + nt * 8 + (lane & 3) * 2;
            {
                int m0 = mask[(size_t)r * MM + c], m1 = mask[(size_t)r * MM + c + 1];
                float2 v;
                v.x = m0 ? acc[mt][nt][0] : NEG;
                v.y = m1 ? acc[mt][nt][1] : NEG;
                *(float2*)(Sg + (size_t)r * MM + c) = v;
            }
            {
                int rr = r + 8;
                int m0 = mask[(size_t)rr * MM + c], m1 = mask[(size_t)rr * MM + c + 1];
                float2 v;
                v.x = m0 ? acc[mt][nt][2] : NEG;
                v.y = m1 ? acc[mt][nt][3] : NEG;
                *(float2*)(Sg + (size_t)rr * MM + c) = v;
            }
        }
}

// ---------------------------------------------------------------------------
// Kernel 3: row softmax -> weights bf16 hi/lo. One CTA (256 thr) per row.
// ---------------------------------------------------------------------------
__global__ __launch_bounds__(256, 1) void softmax_kernel() {
    const int row = blockIdx.x;
    const int tid = threadIdx.x, lane = tid & 31, warp = tid >> 5;
    const float4* S4 = (const float4*)(g_scores + (size_t)row * MM);
    float4 u0 = S4[tid * 2], u1 = S4[tid * 2 + 1];
    float x[8] = {u0.x, u0.y, u0.z, u0.w, u1.x, u1.y, u1.z, u1.w};

    float mx = x[0];
#pragma unroll
    for (int i = 1; i < 8; i++) mx = fmaxf(mx, x[i]);
#pragma unroll
    for (int o = 16; o; o >>= 1) mx = fmaxf(mx, __shfl_xor_sync(0xffffffffu, mx, o));
    __shared__ float redm[8], reds[8];
    if (lane == 0) redm[warp] = mx;
    __syncthreads();
    mx = redm[0];
#pragma unroll
    for (int i = 1; i < 8; i++) mx = fmaxf(mx, redm[i]);

    float e[8], s = 0.f;
#pragma unroll
    for (int i = 0; i < 8; i++) { e[i] = __expf(x[i] - mx); s += e[i]; }
#pragma unroll
    for (int o = 16; o; o >>= 1) s += __shfl_xor_sync(0xffffffffu, s, o);
    if (lane == 0) reds[warp] = s;
    __syncthreads();
    s = reds[0];
#pragma unroll
    for (int i = 1; i < 8; i++) s += reds[i];
    float inv = 1.0f / s;

    __nv_bfloat16 h[8], l[8];
#pragma unroll
    for (int i = 0; i < 8; i++) split1(e[i] * inv, h[i], l[i]);
    uint4 uh, ul;
    __nv_bfloat162* ph = reinterpret_cast<__nv_bfloat162*>(&uh);
    __nv_bfloat162* pl = reinterpret_cast<__nv_bfloat162*>(&ul);
    ph[0] = __halves2bfloat162(h[0], h[1]); ph[1] = __halves2bfloat162(h[2], h[3]);
    ph[2] = __halves2bfloat162(h[4], h[5]); ph[3] = __halves2bfloat162(h[6], h[7]);
    pl[0] = __halves2bfloat162(l[0], l[1]); pl[1] = __halves2bfloat162(l[2], l[3]);
    pl[2] = __halves2bfloat162(l[4], l[5]); pl[3] = __halves2bfloat162(l[6], l[7]);
    *(uint4*)(g_whi + (size_t)row * MM + tid * 8) = uh;
    *(uint4*)(g_wlo + (size_t)row * MM + tid * 8) = ul;
}

// ---------------------------------------------------------------------------
// Kernel 4: out O[b,n,d] = sum_m w[b,n,m] * v[b,m,d]. B is K-major -> trans.
// grid (8 dTiles, 16 nTiles, 8 batch).
// ---------------------------------------------------------------------------
__global__ __launch_bounds__(256, 1) void out_kernel(float* __restrict__ O) {
    __shared__ __align__(16) __nv_bfloat16 sAh[128 * LDA], sAl[128 * LDA];
    __shared__ __align__(16) __nv_bfloat16 sBh[32 * LDBT], sBl[32 * LDBT];
    const int tid = threadIdx.x, lane = tid & 31, warp = tid >> 5;
    const int wm = (warp & 3) * 32, wn = (warp >> 2) * 64;
    const int b = blockIdx.z;
    const int rowBlk = blockIdx.y * 128, colBlk = blockIdx.x * 128;
    const size_t woff = (size_t)b * NN * MM;
    const size_t voff = (size_t)b * MM * DD;

    const int lrowA = tid >> 1, lcolA = (tid & 1) * 16;
    const __nv_bfloat16* pwh = g_whi + woff + (size_t)(rowBlk + lrowA) * MM + lcolA;
    const __nv_bfloat16* pwl = g_wlo + woff + (size_t)(rowBlk + lrowA) * MM + lcolA;
    const int lrowB = tid >> 3, lcolB = (tid & 7) * 16;
    const __nv_bfloat16* pvh = g_vhi + voff + (size_t)lrowB * DD + colBlk + lcolB;
    const __nv_bfloat16* pvl = g_vlo + voff + (size_t)lrowB * DD + colBlk + lcolB;

    float acc[2][8][4] = {};
    for (int k0 = 0; k0 < MM; k0 += 32) {
        const int oA = lrowA * LDA + lcolA;
        *(uint4*)(sAh + oA)     = *(const uint4*)(pwh + k0);
        *(uint4*)(sAh + oA + 8) = *(const uint4*)(pwh + k0 + 8);
        *(uint4*)(sAl + oA)     = *(const uint4*)(pwl + k0);
        *(uint4*)(sAl + oA + 8) = *(const uint4*)(pwl + k0 + 8);
        const int oB = lrowB * LDBT + lcolB;
        const size_t gvo = (size_t)k0 * DD;
        *(uint4*)(sBh + oB)     = *(const uint4*)(pvh + gvo);
        *(uint4*)(sBh + oB + 8) = *(const uint4*)(pvh + gvo + 8);
        *(uint4*)(sBl + oB)     = *(const uint4*)(pvl + gvo);
        *(uint4*)(sBl + oB + 8) = *(const uint4*)(pvl + gvo + 8);
        __syncthreads();
        compute_chunk_t(sAh, sAl, sBh, sBl, wm, wn, lane, acc);
        __syncthreads();
    }

    float* Og = O + (size_t)b * NN * DD;
#pragma unroll
    for (int mt = 0; mt < 2; mt++)
#pragma unroll
        for (int nt = 0; nt < 8; nt++) {
            int r = rowBlk + wm + mt * 16 + (lane >> 2);
            int c = colBlk + wn + nt * 8 + (lane & 3) * 2;
            float2 v0; v0.x = acc[mt][nt][0]; v0.y = acc[mt][nt][1];
            *(float2*)(Og + (size_t)r * DD + c) = v0;
            float2 v1; v1.x = acc[mt][nt][2]; v1.y = acc[mt][nt][3];
            *(float2*)(Og + (size_t)(r + 8) * DD + c) = v1;
        }
}

// ---------------------------------------------------------------------------
// Launch
// ---------------------------------------------------------------------------
extern "C" void kernel_launch(void* const* d_in, const int* in_sizes, int n_in,
                              void* d_out, int out_size) {
    (void)in_sizes; (void)n_in; (void)out_size;
    const float* querys = (const float*)d_in[0];
    const float* keys   = (const float*)d_in[1];
    const float* values = (const float*)d_in[2];
    const int*   mask   = (const int*)d_in[3];
    const float* Wq     = (const float*)d_in[4];
    const float* bq     = (const float*)d_in[5];
    const float* Wk     = (const float*)d_in[6];
    const float* bk     = (const float*)d_in[7];
    const float* Wv     = (const float*)d_in[8];
    const float* bv     = (const float*)d_in[9];
    float* out = (float*)d_out;

    dim3 blk(256);
    proj_kernel<0><<<dim3(8, 128), blk>>>(querys, Wq, bq);
    proj_kernel<1><<<dim3(8, 128), blk>>>(keys,   Wk, bk);
    proj_kernel<2><<<dim3(8, 128), blk>>>(values, Wv, bv);
    score_kernel<<<dim3(16, 16, 8), blk>>>(mask);
    softmax_kernel<<<dim3(16384), blk>>>();
    out_kernel<<<dim3(8, 16, 8), blk>>>(out);
}

// round 4
// speedup vs baseline: 1.4005x; 1.4005x over previous
#include <cuda_runtime.h>
#include <cuda_bf16.h>
#include <cstdint>
#include <cstddef>

// ============================================================================
// Attention_5480378270188 — bf16 hi/lo 3-term mma.sync with cp.async pipeline
// (tcgen05 unavailable: harness PTX target is compute_103, no 'a' features)
// Stages: split -> proj GEMMs -> score GEMM(+mask) -> softmax -> out GEMM
// ============================================================================

#define DEV_INLINE __device__ __forceinline__
typedef __nv_bfloat16 bf16;

constexpr int NN = 2048;
constexpr int MM = 2048;
constexpr int DD = 1024;
constexpr float NEG = -1000000000.0f;

constexpr size_t QKV_ELEMS = (size_t)8 * 2048 * 1024;
constexpr size_t SCORE_ELEMS = (size_t)8 * 2048 * 2048;

// ---------------- device scratch --------------------------------------------
__device__ bf16 g_xqh[QKV_ELEMS], g_xql[QKV_ELEMS];
__device__ bf16 g_xkh[QKV_ELEMS], g_xkl[QKV_ELEMS];
__device__ bf16 g_xvh[QKV_ELEMS], g_xvl[QKV_ELEMS];
__device__ bf16 g_wqh[1024 * 1024], g_wql[1024 * 1024];
__device__ bf16 g_wkh[1024 * 1024], g_wkl[1024 * 1024];
__device__ bf16 g_wvh[1024 * 1024], g_wvl[1024 * 1024];
__device__ bf16 g_qhi[QKV_ELEMS], g_qlo[QKV_ELEMS];
__device__ bf16 g_khi[QKV_ELEMS], g_klo[QKV_ELEMS];
__device__ bf16 g_vhi[QKV_ELEMS], g_vlo[QKV_ELEMS];
__device__ float g_scores[SCORE_ELEMS];
__device__ bf16 g_whi[SCORE_ELEMS], g_wlo[SCORE_ELEMS];

#define LDA  40    // 128 x (32+8) bf16; 80B row = 5*16B (cp.async aligned)
#define LDBT 136   // 32 x (128+8) bf16; 272B row = 17*16B

// ---------------- PTX helpers -----------------------------------------------
DEV_INLINE uint32_t smem_u32(const void* p) { return (uint32_t)__cvta_generic_to_shared(p); }

DEV_INLINE void cp16(void* dst, const void* src) {
    uint32_t d = smem_u32(dst);
    asm volatile("cp.async.cg.shared.global [%0], [%1], 16;\n"
                 :: "r"(d), "l"(__cvta_generic_to_global(src)) : "memory");
}
#define CP_COMMIT() asm volatile("cp.async.commit_group;\n" ::: "memory")
#define CP_WAIT2()  asm volatile("cp.async.wait_group 2;\n" ::: "memory")

DEV_INLINE void ldsm4(uint32_t r[4], const void* p) {
    uint32_t a = smem_u32(p);
    asm volatile("ldmatrix.sync.aligned.m8n8.x4.shared.b16 {%0,%1,%2,%3}, [%4];\n"
                 : "=r"(r[0]), "=r"(r[1]), "=r"(r[2]), "=r"(r[3]) : "r"(a));
}
DEV_INLINE void ldsm4t(uint32_t r[4], const void* p) {
    uint32_t a = smem_u32(p);
    asm volatile("ldmatrix.sync.aligned.m8n8.x4.trans.shared.b16 {%0,%1,%2,%3}, [%4];\n"
                 : "=r"(r[0]), "=r"(r[1]), "=r"(r[2]), "=r"(r[3]) : "r"(a));
}
DEV_INLINE void mma16816(float c[4], const uint32_t a[4], uint32_t b0, uint32_t b1) {
    asm volatile(
        "mma.sync.aligned.m16n8k16.row.col.f32.bf16.bf16.f32 "
        "{%0,%1,%2,%3},{%4,%5,%6,%7},{%8,%9},{%0,%1,%2,%3};\n"
        : "+f"(c[0]), "+f"(c[1]), "+f"(c[2]), "+f"(c[3])
        : "r"(a[0]), "r"(a[1]), "r"(a[2]), "r"(a[3]), "r"(b0), "r"(b1));
}
DEV_INLINE void split1(float v, bf16& h, bf16& l) {
    h = __float2bfloat16(v);
    l = __float2bfloat16(v - __bfloat162float(h));
}

// ---------------- compute cores (unchanged from validated baseline) ---------
DEV_INLINE void compute_chunk_nt(const bf16* sAh, const bf16* sAl,
                                 const bf16* sBh, const bf16* sBl,
                                 int wm, int wn, int lane, float (&acc)[2][8][4]) {
#pragma unroll
    for (int kk = 0; kk < 32; kk += 16) {
        uint32_t ah[2][4], al[2][4], bh[4][4], bl[4][4];
#pragma unroll
        for (int mt = 0; mt < 2; mt++) {
            int r = wm + mt * 16 + (lane & 15);
            int c = kk + (lane >> 4) * 8;
            ldsm4(ah[mt], sAh + r * LDA + c);
            ldsm4(al[mt], sAl + r * LDA + c);
        }
#pragma unroll
        for (int p = 0; p < 4; p++) {
            int r = wn + p * 16 + (lane >> 4) * 8 + (lane & 7);
            int c = kk + ((lane >> 3) & 1) * 8;
            ldsm4(bh[p], sBh + r * LDA + c);
            ldsm4(bl[p], sBl + r * LDA + c);
        }
#pragma unroll
        for (int mt = 0; mt < 2; mt++)
#pragma unroll
            for (int p = 0; p < 4; p++) {
                mma16816(acc[mt][2 * p],     ah[mt], bh[p][0], bh[p][1]);
                mma16816(acc[mt][2 * p],     ah[mt], bl[p][0], bl[p][1]);
                mma16816(acc[mt][2 * p],     al[mt], bh[p][0], bh[p][1]);
                mma16816(acc[mt][2 * p + 1], ah[mt], bh[p][2], bh[p][3]);
                mma16816(acc[mt][2 * p + 1], ah[mt], bl[p][2], bl[p][3]);
                mma16816(acc[mt][2 * p + 1], al[mt], bh[p][2], bh[p][3]);
            }
    }
}

DEV_INLINE void compute_chunk_t(const bf16* sAh, const bf16* sAl,
                                const bf16* sBh, const bf16* sBl,
                                int wm, int wn, int lane, float (&acc)[2][8][4]) {
#pragma unroll
    for (int kk = 0; kk < 32; kk += 16) {
        uint32_t ah[2][4], al[2][4], bh[4][4], bl[4][4];
#pragma unroll
        for (int mt = 0; mt < 2; mt++) {
            int r = wm + mt * 16 + (lane & 15);
            int c = kk + (lane >> 4) * 8;
            ldsm4(ah[mt], sAh + r * LDA + c);
            ldsm4(al[mt], sAl + r * LDA + c);
        }
#pragma unroll
        for (int p = 0; p < 4; p++) {
            int r = kk + ((lane >> 3) & 1) * 8 + (lane & 7);
            int c = wn + p * 16 + (lane >> 4) * 8;
            ldsm4t(bh[p], sBh + r * LDBT + c);
            ldsm4t(bl[p], sBl + r * LDBT + c);
        }
#pragma unroll
        for (int mt = 0; mt < 2; mt++)
#pragma unroll
            for (int p = 0; p < 4; p++) {
                mma16816(acc[mt][2 * p],     ah[mt], bh[p][0], bh[p][1]);
                mma16816(acc[mt][2 * p],     ah[mt], bl[p][0], bl[p][1]);
                mma16816(acc[mt][2 * p],     al[mt], bh[p][0], bh[p][1]);
                mma16816(acc[mt][2 * p + 1], ah[mt], bh[p][2], bh[p][3]);
                mma16816(acc[mt][2 * p + 1], ah[mt], bl[p][2], bl[p][3]);
                mma16816(acc[mt][2 * p + 1], al[mt], bh[p][2], bh[p][3]);
            }
    }
}

// ---------------------------------------------------------------------------
// Pipelined NT GEMM (A[rows,1024] hi/lo  x  B[cols,1024] hi/lo, K=1024)
// EPI 0: proj -> bias + split -> Chi/Clo [row,1024]
// EPI 1: score -> mask -> g_scores fp32 [row,2048]
// SEL 0: q proj, 1: k proj, 2: v proj, 3: score
// ---------------------------------------------------------------------------
constexpr int TILE_NT = 128 * LDA;                 // bf16 elems per tile
constexpr int STAGE_NT = 4 * TILE_NT * 2;          // bytes (40960)
constexpr int SMEM_NT = 3 * STAGE_NT;              // 122880

template <int EPI, int SEL>
__global__ __launch_bounds__(256, 1) void gemm_nt(const float* __restrict__ bias,
                                                  const int* __restrict__ mask) {
    extern __shared__ char ds[];
    const int tid = threadIdx.x, lane = tid & 31, warp = tid >> 5;
    const int wm = (warp & 3) * 32, wn = (warp >> 2) * 64;
    const int rowBlk = blockIdx.y * 128, colBlk = blockIdx.x * 128;
    const int z = blockIdx.z;

    const bf16 *Ah, *Al, *Bh, *Bl;
    if constexpr (SEL == 0) { Ah = g_xqh; Al = g_xql; Bh = g_wqh; Bl = g_wql; }
    else if constexpr (SEL == 1) { Ah = g_xkh; Al = g_xkl; Bh = g_wkh; Bl = g_wkl; }
    else if constexpr (SEL == 2) { Ah = g_xvh; Al = g_xvl; Bh = g_wvh; Bl = g_wvl; }
    else { Ah = g_qhi; Al = g_qlo; Bh = g_khi; Bl = g_klo; }
    const size_t zoff = (SEL == 3) ? (size_t)z * 2048 * 1024 : 0;
    const bf16* Ahp = Ah + zoff;  const bf16* Alp = Al + zoff;
    const bf16* Bhp = Bh + zoff;  const bf16* Blp = Bl + zoff;

    auto issue = [&](int s, int k0) {
        char* st = ds + s * STAGE_NT;
        bf16* dAh = (bf16*)st;
        bf16* dAl = dAh + TILE_NT;
        bf16* dBh = dAl + TILE_NT;
        bf16* dBl = dBh + TILE_NT;
#pragma unroll
        for (int i = 0; i < 2; i++) {
            int u = tid + 256 * i, r = u >> 2, q = (u & 3) * 8;
            size_t ga = (size_t)(rowBlk + r) * 1024 + k0 + q;
            size_t gb = (size_t)(colBlk + r) * 1024 + k0 + q;
            cp16(dAh + r * LDA + q, Ahp + ga);
            cp16(dAl + r * LDA + q, Alp + ga);
            cp16(dBh + r * LDA + q, Bhp + gb);
            cp16(dBl + r * LDA + q, Blp + gb);
        }
    };

    float acc[2][8][4] = {};
    issue(0, 0);  CP_COMMIT();
    issue(1, 32); CP_COMMIT();
    for (int it = 0; it < 32; it++) {
        if (it + 2 < 32) issue((it + 2) % 3, (it + 2) * 32);
        CP_COMMIT();
        CP_WAIT2();
        __syncthreads();
        char* st = ds + (it % 3) * STAGE_NT;
        bf16* sAh = (bf16*)st;
        compute_chunk_nt(sAh, sAh + TILE_NT, sAh + 2 * TILE_NT, sAh + 3 * TILE_NT,
                         wm, wn, lane, acc);
        __syncthreads();
    }

    if constexpr (EPI == 0) {
        bf16 *Chi, *Clo;
        if constexpr (SEL == 0) { Chi = g_qhi; Clo = g_qlo; }
        else if constexpr (SEL == 1) { Chi = g_khi; Clo = g_klo; }
        else { Chi = g_vhi; Clo = g_vlo; }
#pragma unroll
        for (int mt = 0; mt < 2; mt++)
#pragma unroll
            for (int nt = 0; nt < 8; nt++) {
                int r = rowBlk + wm + mt * 16 + (lane >> 2);
                int c = colBlk + wn + nt * 8 + (lane & 3) * 2;
                float b0 = bias[c], b1 = bias[c + 1];
                {
                    bf16 h0, l0, h1, l1;
                    split1(acc[mt][nt][0] + b0, h0, l0);
                    split1(acc[mt][nt][1] + b1, h1, l1);
                    *(__nv_bfloat162*)(Chi + (size_t)r * 1024 + c) = __halves2bfloat162(h0, h1);
                    *(__nv_bfloat162*)(Clo + (size_t)r * 1024 + c) = __halves2bfloat162(l0, l1);
                }
                {
                    bf16 h0, l0, h1, l1;
                    split1(acc[mt][nt][2] + b0, h0, l0);
                    split1(acc[mt][nt][3] + b1, h1, l1);
                    *(__nv_bfloat162*)(Chi + (size_t)(r + 8) * 1024 + c) = __halves2bfloat162(h0, h1);
                    *(__nv_bfloat162*)(Clo + (size_t)(r + 8) * 1024 + c) = __halves2bfloat162(l0, l1);
                }
            }
    } else {
        float* Sg = g_scores + (size_t)z * NN * MM;
#pragma unroll
        for (int mt = 0; mt < 2; mt++)
#pragma unroll
            for (int nt = 0; nt < 8; nt++) {
                int r = rowBlk + wm + mt * 16 + (lane >> 2);
                int c = colBlk + wn + nt * 8 + (lane & 3) * 2;
                {
                    int m0 = mask[(size_t)r * MM + c], m1 = mask[(size_t)r * MM + c + 1];
                    float2 v;
                    v.x = m0 ? acc[mt][nt][0] : NEG;
                    v.y = m1 ? acc[mt][nt][1] : NEG;
                    *(float2*)(Sg + (size_t)r * MM + c) = v;
                }
                {
                    int rr = r + 8;
                    int m0 = mask[(size_t)rr * MM + c], m1 = mask[(size_t)rr * MM + c + 1];
                    float2 v;
                    v.x = m0 ? acc[mt][nt][2] : NEG;
                    v.y = m1 ? acc[mt][nt][3] : NEG;
                    *(float2*)(Sg + (size_t)rr * MM + c) = v;
                }
            }
    }
}

// ---------------------------------------------------------------------------
// Pipelined out GEMM: O[b,n,d] = sum_m w[b,n,m] v[b,m,d]; B via ldmatrix.trans
// ---------------------------------------------------------------------------
constexpr int TILE_A = 128 * LDA;        // elems
constexpr int TILE_B = 32 * LDBT;        // elems
constexpr int STAGE_T = (2 * TILE_A + 2 * TILE_B) * 2;   // 37888 bytes
constexpr int SMEM_T = 3 * STAGE_T;                      // 113664

__global__ __launch_bounds__(256, 1) void out_kernel(float* __restrict__ O) {
    extern __shared__ char ds[];
    const int tid = threadIdx.x, lane = tid & 31, warp = tid >> 5;
    const int wm = (warp & 3) * 32, wn = (warp >> 2) * 64;
    const int z = blockIdx.z;
    const int rowBlk = blockIdx.y * 128, colBlk = blockIdx.x * 128;
    const bf16* wh = g_whi + (size_t)z * NN * MM;
    const bf16* wl = g_wlo + (size_t)z * NN * MM;
    const bf16* vh = g_vhi + (size_t)z * MM * DD;
    const bf16* vl = g_vlo + (size_t)z * MM * DD;

    auto issue = [&](int s, int k0) {
        char* st = ds + s * STAGE_T;
        bf16* dAh = (bf16*)st;
        bf16* dAl = dAh + TILE_A;
        bf16* dBh = dAl + TILE_A;
        bf16* dBl = dBh + TILE_B;
#pragma unroll
        for (int i = 0; i < 2; i++) {
            int u = tid + 256 * i;
            {
                int r = u >> 2, q = (u & 3) * 8;
                size_t ga = (size_t)(rowBlk + r) * MM + k0 + q;
                cp16(dAh + r * LDA + q, wh + ga);
                cp16(dAl + r * LDA + q, wl + ga);
            }
            {
                int r = u >> 4, q = (u & 15) * 8;
                size_t gb = (size_t)(k0 + r) * DD + colBlk + q;
                cp16(dBh + r * LDBT + q, vh + gb);
                cp16(dBl + r * LDBT + q, vl + gb);
            }
        }
    };

    float acc[2][8][4] = {};
    issue(0, 0);  CP_COMMIT();
    issue(1, 32); CP_COMMIT();
    for (int it = 0; it < 64; it++) {
        if (it + 2 < 64) issue((it + 2) % 3, (it + 2) * 32);
        CP_COMMIT();
        CP_WAIT2();
        __syncthreads();
        char* st = ds + (it % 3) * STAGE_T;
        bf16* sAh = (bf16*)st;
        compute_chunk_t(sAh, sAh + TILE_A, sAh + 2 * TILE_A, sAh + 2 * TILE_A + TILE_B,
                        wm, wn, lane, acc);
        __syncthreads();
    }

    float* Og = O + (size_t)z * NN * DD;
#pragma unroll
    for (int mt = 0; mt < 2; mt++)
#pragma unroll
        for (int nt = 0; nt < 8; nt++) {
            int r = rowBlk + wm + mt * 16 + (lane >> 2);
            int c = colBlk + wn + nt * 8 + (lane & 3) * 2;
            float2 v0; v0.x = acc[mt][nt][0]; v0.y = acc[mt][nt][1];
            *(float2*)(Og + (size_t)r * DD + c) = v0;
            float2 v1; v1.x = acc[mt][nt][2]; v1.y = acc[mt][nt][3];
            *(float2*)(Og + (size_t)(r + 8) * DD + c) = v1;
        }
}

// ---------------------------------------------------------------------------
// split: fp32 [rows,1024] -> hi/lo bf16 arrays
// ---------------------------------------------------------------------------
template <int SEL>
__global__ __launch_bounds__(256, 4) void split_k(const float* __restrict__ X) {
    bf16 *H, *L;
    if constexpr (SEL == 0) { H = g_xqh; L = g_xql; }
    else if constexpr (SEL == 1) { H = g_xkh; L = g_xkl; }
    else if constexpr (SEL == 2) { H = g_xvh; L = g_xvl; }
    else if constexpr (SEL == 3) { H = g_wqh; L = g_wql; }
    else if constexpr (SEL == 4) { H = g_wkh; L = g_wkl; }
    else { H = g_wvh; L = g_wvl; }
    size_t row = blockIdx.x;
    int t = threadIdx.x;
    float4 v = ((const float4*)(X + row * 1024))[t];
    bf16 h0, l0, h1, l1, h2, l2, h3, l3;
    split1(v.x, h0, l0); split1(v.y, h1, l1);
    split1(v.z, h2, l2); split1(v.w, h3, l3);
    bf16* ph = H + row * 1024 + t * 4;
    bf16* pl = L + row * 1024 + t * 4;
    *(__nv_bfloat162*)(ph)     = __halves2bfloat162(h0, h1);
    *(__nv_bfloat162*)(ph + 2) = __halves2bfloat162(h2, h3);
    *(__nv_bfloat162*)(pl)     = __halves2bfloat162(l0, l1);
    *(__nv_bfloat162*)(pl + 2) = __halves2bfloat162(l2, l3);
}

// ---------------------------------------------------------------------------
// softmax: scores row -> weights hi/lo
// ---------------------------------------------------------------------------
__global__ __launch_bounds__(256, 1) void softmax_kernel() {
    const int row = blockIdx.x;
    const int tid = threadIdx.x, lane = tid & 31, warp = tid >> 5;
    const float4* S4 = (const float4*)(g_scores + (size_t)row * MM);
    float4 u0 = S4[tid * 2], u1 = S4[tid * 2 + 1];
    float x[8] = {u0.x, u0.y, u0.z, u0.w, u1.x, u1.y, u1.z, u1.w};

    float mx = x[0];
#pragma unroll
    for (int i = 1; i < 8; i++) mx = fmaxf(mx, x[i]);
#pragma unroll
    for (int o = 16; o; o >>= 1) mx = fmaxf(mx, __shfl_xor_sync(0xffffffffu, mx, o));
    __shared__ float redm[8], reds[8];
    if (lane == 0) redm[warp] = mx;
    __syncthreads();
    mx = redm[0];
#pragma unroll
    for (int i = 1; i < 8; i++) mx = fmaxf(mx, redm[i]);

    float e[8], s = 0.f;
#pragma unroll
    for (int i = 0; i < 8; i++) { e[i] = __expf(x[i] - mx); s += e[i]; }
#pragma unroll
    for (int o = 16; o; o >>= 1) s += __shfl_xor_sync(0xffffffffu, s, o);
    if (lane == 0) reds[warp] = s;
    __syncthreads();
    s = reds[0];
#pragma unroll
    for (int i = 1; i < 8; i++) s += reds[i];
    float inv = 1.0f / s;

    bf16 h[8], l[8];
#pragma unroll
    for (int i = 0; i < 8; i++) split1(e[i] * inv, h[i], l[i]);
    uint4 uh, ul;
    __nv_bfloat162* ph = reinterpret_cast<__nv_bfloat162*>(&uh);
    __nv_bfloat162* pl = reinterpret_cast<__nv_bfloat162*>(&ul);
    ph[0] = __halves2bfloat162(h[0], h[1]); ph[1] = __halves2bfloat162(h[2], h[3]);
    ph[2] = __halves2bfloat162(h[4], h[5]); ph[3] = __halves2bfloat162(h[6], h[7]);
    pl[0] = __halves2bfloat162(l[0], l[1]); pl[1] = __halves2bfloat162(l[2], l[3]);
    pl[2] = __halves2bfloat162(l[4], l[5]); pl[3] = __halves2bfloat162(l[6], l[7]);
    *(uint4*)(g_whi + (size_t)row * MM + tid * 8) = uh;
    *(uint4*)(g_wlo + (size_t)row * MM + tid * 8) = ul;
}

// ---------------------------------------------------------------------------
// Launch
// ---------------------------------------------------------------------------
extern "C" void kernel_launch(void* const* d_in, const int* in_sizes, int n_in,
                              void* d_out, int out_size) {
    (void)in_sizes; (void)n_in; (void)out_size;
    const float* querys = (const float*)d_in[0];
    const float* keys   = (const float*)d_in[1];
    const float* values = (const float*)d_in[2];
    const int*   mask   = (const int*)d_in[3];
    const float* Wq     = (const float*)d_in[4];
    const float* bq     = (const float*)d_in[5];
    const float* Wk     = (const float*)d_in[6];
    const float* bk     = (const float*)d_in[7];
    const float* Wv     = (const float*)d_in[8];
    const float* bv     = (const float*)d_in[9];
    float* out = (float*)d_out;

    static bool attr_done = false;
    if (!attr_done) {
        cudaFuncSetAttribute(gemm_nt<0, 0>, cudaFuncAttributeMaxDynamicSharedMemorySize, SMEM_NT);
        cudaFuncSetAttribute(gemm_nt<0, 1>, cudaFuncAttributeMaxDynamicSharedMemorySize, SMEM_NT);
        cudaFuncSetAttribute(gemm_nt<0, 2>, cudaFuncAttributeMaxDynamicSharedMemorySize, SMEM_NT);
        cudaFuncSetAttribute(gemm_nt<1, 3>, cudaFuncAttributeMaxDynamicSharedMemorySize, SMEM_NT);
        cudaFuncSetAttribute(out_kernel, cudaFuncAttributeMaxDynamicSharedMemorySize, SMEM_T);
        attr_done = true;
    }

    dim3 blk(256);
    split_k<0><<<16384, blk>>>(querys);
    split_k<1><<<16384, blk>>>(keys);
    split_k<2><<<16384, blk>>>(values);
    split_k<3><<<1024, blk>>>(Wq);
    split_k<4><<<1024, blk>>>(Wk);
    split_k<5><<<1024, blk>>>(Wv);

    gemm_nt<0, 0><<<dim3(8, 128, 1), blk, SMEM_NT>>>(bq, nullptr);
    gemm_nt<0, 1><<<dim3(8, 128, 1), blk, SMEM_NT>>>(bk, nullptr);
    gemm_nt<0, 2><<<dim3(8, 128, 1), blk, SMEM_NT>>>(bv, nullptr);

    gemm_nt<1, 3><<<dim3(16, 16, 8), blk, SMEM_NT>>>(nullptr, mask);

    softmax_kernel<<<16384, blk>>>();

    out_kernel<<<dim3(8, 16, 8), blk, SMEM_T>>>(out);
}

// round 5
// speedup vs baseline: 1.5344x; 1.0956x over previous
#include <cuda_runtime.h>
#include <cuda_bf16.h>
#include <cstdint>
#include <cstddef>

// ============================================================================
// Attention_5480378270188 — bf16 hi/lo 3-term mma.sync, cp.async 3-stage,
// 128x256 CTA tile, 512 threads, single-sync pipeline, term-looped B-reg reuse
// ============================================================================

#define DEV_INLINE __device__ __forceinline__
typedef __nv_bfloat16 bf16;

constexpr int NN = 2048;
constexpr int MM = 2048;
constexpr int DD = 1024;
constexpr float NEG = -1000000000.0f;

constexpr size_t QKV_ELEMS = (size_t)8 * 2048 * 1024;
constexpr size_t SCORE_ELEMS = (size_t)8 * 2048 * 2048;

// ---------------- device scratch --------------------------------------------
__device__ bf16 g_xqh[QKV_ELEMS], g_xql[QKV_ELEMS];
__device__ bf16 g_xkh[QKV_ELEMS], g_xkl[QKV_ELEMS];
__device__ bf16 g_xvh[QKV_ELEMS], g_xvl[QKV_ELEMS];
__device__ bf16 g_wqh[1024 * 1024], g_wql[1024 * 1024];
__device__ bf16 g_wkh[1024 * 1024], g_wkl[1024 * 1024];
__device__ bf16 g_wvh[1024 * 1024], g_wvl[1024 * 1024];
__device__ bf16 g_qhi[QKV_ELEMS], g_qlo[QKV_ELEMS];
__device__ bf16 g_khi[QKV_ELEMS], g_klo[QKV_ELEMS];
__device__ bf16 g_vhi[QKV_ELEMS], g_vlo[QKV_ELEMS];
__device__ float g_scores[SCORE_ELEMS];
__device__ bf16 g_whi[SCORE_ELEMS], g_wlo[SCORE_ELEMS];

#define LDA  40    // K-major tiles: rows x (32+8) bf16, 80B rows
#define LDBT 264   // out-kernel B tile: 32 x (256+8) bf16, 528B rows

// ---------------- PTX helpers -----------------------------------------------
DEV_INLINE uint32_t smem_u32(const void* p) { return (uint32_t)__cvta_generic_to_shared(p); }

DEV_INLINE void cp16(void* dst, const void* src) {
    uint32_t d = smem_u32(dst);
    asm volatile("cp.async.cg.shared.global [%0], [%1], 16;\n"
                 :: "r"(d), "l"(__cvta_generic_to_global(src)) : "memory");
}
#define CP_COMMIT() asm volatile("cp.async.commit_group;\n" ::: "memory")
#define CP_WAIT1()  asm volatile("cp.async.wait_group 1;\n" ::: "memory")

DEV_INLINE void ldsm4(uint32_t r[4], const void* p) {
    uint32_t a = smem_u32(p);
    asm volatile("ldmatrix.sync.aligned.m8n8.x4.shared.b16 {%0,%1,%2,%3}, [%4];\n"
                 : "=r"(r[0]), "=r"(r[1]), "=r"(r[2]), "=r"(r[3]) : "r"(a));
}
DEV_INLINE void ldsm4t(uint32_t r[4], const void* p) {
    uint32_t a = smem_u32(p);
    asm volatile("ldmatrix.sync.aligned.m8n8.x4.trans.shared.b16 {%0,%1,%2,%3}, [%4];\n"
                 : "=r"(r[0]), "=r"(r[1]), "=r"(r[2]), "=r"(r[3]) : "r"(a));
}
DEV_INLINE void mma16816(float c[4], const uint32_t a[4], uint32_t b0, uint32_t b1) {
    asm volatile(
        "mma.sync.aligned.m16n8k16.row.col.f32.bf16.bf16.f32 "
        "{%0,%1,%2,%3},{%4,%5,%6,%7},{%8,%9},{%0,%1,%2,%3};\n"
        : "+f"(c[0]), "+f"(c[1]), "+f"(c[2]), "+f"(c[3])
        : "r"(a[0]), "r"(a[1]), "r"(a[2]), "r"(a[3]), "r"(b0), "r"(b1));
}
DEV_INLINE void split1(float v, bf16& h, bf16& l) {
    h = __float2bfloat16(v);
    l = __float2bfloat16(v - __bfloat162float(h));
}

// ---------------- stage layout constants ------------------------------------
// proj/score stage: [Ah 128x40][Al 128x40][Bh 256x40][Bl 256x40] bf16
constexpr int TA_E = 128 * LDA;                 // 5120 elems
constexpr int TB_E = 256 * LDA;                 // 10240 elems
constexpr int STAGE_NT_E = 2 * TA_E + 2 * TB_E; // 30720 elems
constexpr int SMEM_NT = 3 * STAGE_NT_E * 2;     // 184320 B
// out stage: [Ah 128x40][Al 128x40][Bh 32x264][Bl 32x264]
constexpr int TBT_E = 32 * LDBT;                // 8448 elems
constexpr int STAGE_T_E = 2 * TA_E + 2 * TBT_E; // 27136 elems
constexpr int SMEM_T = 3 * STAGE_T_E * 2;       // 162816 B

// ---------------- compute cores ---------------------------------------------
// NT: both operands K-major in tiles of LDA. Warp tile 32(m) x 64(n).
DEV_INLINE void compute_nt(const bf16* st, int wm, int wn, int lane,
                           float (&acc)[2][8][4]) {
    const bf16* sAh = st;
    const bf16* sAl = st + TA_E;
    const bf16* sBh = st + 2 * TA_E;
    const bf16* sBl = st + 2 * TA_E + TB_E;
#pragma unroll
    for (int kk = 0; kk < 32; kk += 16) {
        uint32_t ah[2][4], al[2][4], b[4][4];
        const int ar = (lane & 15), ac = kk + (lane >> 4) * 8;
#pragma unroll
        for (int mt = 0; mt < 2; mt++) {
            int r = wm + mt * 16 + ar;
            ldsm4(ah[mt], sAh + r * LDA + ac);
            ldsm4(al[mt], sAl + r * LDA + ac);
        }
        const int br0 = (lane >> 4) * 8 + (lane & 7);
        const int bc = kk + ((lane >> 3) & 1) * 8;
#pragma unroll
        for (int p = 0; p < 4; p++)
            ldsm4(b[p], sBh + (wn + p * 16 + br0) * LDA + bc);
#pragma unroll
        for (int mt = 0; mt < 2; mt++)
#pragma unroll
            for (int p = 0; p < 4; p++) {
                mma16816(acc[mt][2 * p],     ah[mt], b[p][0], b[p][1]);
                mma16816(acc[mt][2 * p + 1], ah[mt], b[p][2], b[p][3]);
                mma16816(acc[mt][2 * p],     al[mt], b[p][0], b[p][1]);
                mma16816(acc[mt][2 * p + 1], al[mt], b[p][2], b[p][3]);
            }
#pragma unroll
        for (int p = 0; p < 4; p++)
            ldsm4(b[p], sBl + (wn + p * 16 + br0) * LDA + bc);
#pragma unroll
        for (int mt = 0; mt < 2; mt++)
#pragma unroll
            for (int p = 0; p < 4; p++) {
                mma16816(acc[mt][2 * p],     ah[mt], b[p][0], b[p][1]);
                mma16816(acc[mt][2 * p + 1], ah[mt], b[p][2], b[p][3]);
            }
    }
}

// T: B stored [k=32][n=256+pad], loaded via ldmatrix.trans
DEV_INLINE void compute_t(const bf16* st, int wm, int wn, int lane,
                          float (&acc)[2][8][4]) {
    const bf16* sAh = st;
    const bf16* sAl = st + TA_E;
    const bf16* sBh = st + 2 * TA_E;
    const bf16* sBl = st + 2 * TA_E + TBT_E;
#pragma unroll
    for (int kk = 0; kk < 32; kk += 16) {
        uint32_t ah[2][4], al[2][4], b[4][4];
        const int ar = (lane & 15), ac = kk + (lane >> 4) * 8;
#pragma unroll
        for (int mt = 0; mt < 2; mt++) {
            int r = wm + mt * 16 + ar;
            ldsm4(ah[mt], sAh + r * LDA + ac);
            ldsm4(al[mt], sAl + r * LDA + ac);
        }
        const int br = kk + ((lane >> 3) & 1) * 8 + (lane & 7);
        const int bc0 = wn + (lane >> 4) * 8;
#pragma unroll
        for (int p = 0; p < 4; p++)
            ldsm4t(b[p], sBh + br * LDBT + bc0 + p * 16);
#pragma unroll
        for (int mt = 0; mt < 2; mt++)
#pragma unroll
            for (int p = 0; p < 4; p++) {
                mma16816(acc[mt][2 * p],     ah[mt], b[p][0], b[p][1]);
                mma16816(acc[mt][2 * p + 1], ah[mt], b[p][2], b[p][3]);
                mma16816(acc[mt][2 * p],     al[mt], b[p][0], b[p][1]);
                mma16816(acc[mt][2 * p + 1], al[mt], b[p][2], b[p][3]);
            }
#pragma unroll
        for (int p = 0; p < 4; p++)
            ldsm4t(b[p], sBl + br * LDBT + bc0 + p * 16);
#pragma unroll
        for (int mt = 0; mt < 2; mt++)
#pragma unroll
            for (int p = 0; p < 4; p++) {
                mma16816(acc[mt][2 * p],     ah[mt], b[p][0], b[p][1]);
                mma16816(acc[mt][2 * p + 1], ah[mt], b[p][2], b[p][3]);
            }
    }
}

// ---------------------------------------------------------------------------
// gemm512<EPI,SEL>: A[rows,1024] hi/lo x B[cols,1024] hi/lo  (K=1024, NT)
// EPI 0: proj -> bias+split; EPI 1: score -> mask -> fp32
// SEL: 0 q, 1 k, 2 v, 3 score
// ---------------------------------------------------------------------------
template <int EPI, int SEL>
__global__ __launch_bounds__(512, 1) void gemm512(const float* __restrict__ bias,
                                                  const int* __restrict__ mask) {
    extern __shared__ char ds[];
    const int tid = threadIdx.x, lane = tid & 31, warp = tid >> 5;
    const int wm = (warp & 3) * 32, wn = (warp >> 2) * 64;
    const int rowBlk = blockIdx.y * 128, colBlk = blockIdx.x * 256;
    const int z = blockIdx.z;

    const bf16 *Ah, *Al, *Bh, *Bl;
    if constexpr (SEL == 0) { Ah = g_xqh; Al = g_xql; Bh = g_wqh; Bl = g_wql; }
    else if constexpr (SEL == 1) { Ah = g_xkh; Al = g_xkl; Bh = g_wkh; Bl = g_wkl; }
    else if constexpr (SEL == 2) { Ah = g_xvh; Al = g_xvl; Bh = g_wvh; Bl = g_wvl; }
    else { Ah = g_qhi; Al = g_qlo; Bh = g_khi; Bl = g_klo; }
    const size_t zoff = (SEL == 3) ? (size_t)z * 2048 * 1024 : 0;
    const bf16* Ahp = Ah + zoff;  const bf16* Alp = Al + zoff;
    const bf16* Bhp = Bh + zoff;  const bf16* Blp = Bl + zoff;

    auto issue = [&](int s, int chunk) {
        bf16* st = (bf16*)ds + s * STAGE_NT_E;
        const int k0 = chunk * 32;
        {   // A: 128 rows x 4 x 16B ; one cp per array per thread
            int r = tid >> 2, q = (tid & 3) * 8;
            size_t ga = (size_t)(rowBlk + r) * 1024 + k0 + q;
            cp16(st + r * LDA + q, Ahp + ga);
            cp16(st + TA_E + r * LDA + q, Alp + ga);
        }
#pragma unroll
        for (int i = 0; i < 2; i++) {  // B: 256 rows
            int u = tid + 512 * i, r = u >> 2, q = (u & 3) * 8;
            size_t gb = (size_t)(colBlk + r) * 1024 + k0 + q;
            cp16(st + 2 * TA_E + r * LDA + q, Bhp + gb);
            cp16(st + 2 * TA_E + TB_E + r * LDA + q, Blp + gb);
        }
    };

    float acc[2][8][4] = {};
    issue(0, 0); CP_COMMIT();
    issue(1, 1); CP_COMMIT();
    for (int it = 0; it < 32; it++) {
        CP_WAIT1();
        __syncthreads();
        if (it + 2 < 32) issue((it + 2) % 3, it + 2);
        CP_COMMIT();
        compute_nt((bf16*)ds + (it % 3) * STAGE_NT_E, wm, wn, lane, acc);
    }

    if constexpr (EPI == 0) {
        bf16 *Chi, *Clo;
        if constexpr (SEL == 0) { Chi = g_qhi; Clo = g_qlo; }
        else if constexpr (SEL == 1) { Chi = g_khi; Clo = g_klo; }
        else { Chi = g_vhi; Clo = g_vlo; }
#pragma unroll
        for (int mt = 0; mt < 2; mt++)
#pragma unroll
            for (int nt = 0; nt < 8; nt++) {
                int r = rowBlk + wm + mt * 16 + (lane >> 2);
                int c = colBlk + wn + nt * 8 + (lane & 3) * 2;
                float b0 = bias[c], b1 = bias[c + 1];
                {
                    bf16 h0, l0, h1, l1;
                    split1(acc[mt][nt][0] + b0, h0, l0);
                    split1(acc[mt][nt][1] + b1, h1, l1);
                    *(__nv_bfloat162*)(Chi + (size_t)r * 1024 + c) = __halves2bfloat162(h0, h1);
                    *(__nv_bfloat162*)(Clo + (size_t)r * 1024 + c) = __halves2bfloat162(l0, l1);
                }
                {
                    bf16 h0, l0, h1, l1;
                    split1(acc[mt][nt][2] + b0, h0, l0);
                    split1(acc[mt][nt][3] + b1, h1, l1);
                    *(__nv_bfloat162*)(Chi + (size_t)(r + 8) * 1024 + c) = __halves2bfloat162(h0, h1);
                    *(__nv_bfloat162*)(Clo + (size_t)(r + 8) * 1024 + c) = __halves2bfloat162(l0, l1);
                }
            }
    } else {
        float* Sg = g_scores + (size_t)z * NN * MM;
#pragma unroll
        for (int mt = 0; mt < 2; mt++)
#pragma unroll
            for (int nt = 0; nt < 8; nt++) {
                int r = rowBlk + wm + mt * 16 + (lane >> 2);
                int c = colBlk + wn + nt * 8 + (lane & 3) * 2;
                {
                    int m0 = mask[(size_t)r * MM + c], m1 = mask[(size_t)r * MM + c + 1];
                    float2 v;
                    v.x = m0 ? acc[mt][nt][0] : NEG;
                    v.y = m1 ? acc[mt][nt][1] : NEG;
                    *(float2*)(Sg + (size_t)r * MM + c) = v;
                }
                {
                    int rr = r + 8;
                    int m0 = mask[(size_t)rr * MM + c], m1 = mask[(size_t)rr * MM + c + 1];
                    float2 v;
                    v.x = m0 ? acc[mt][nt][2] : NEG;
                    v.y = m1 ? acc[mt][nt][3] : NEG;
                    *(float2*)(Sg + (size_t)rr * MM + c) = v;
                }
            }
    }
}

// ---------------------------------------------------------------------------
// out512: O[b,n,d] = sum_m w[b,n,m] v[b,m,d]; B via ldmatrix.trans, K=2048
// ---------------------------------------------------------------------------
__global__ __launch_bounds__(512, 1) void out512(float* __restrict__ O) {
    extern __shared__ char ds[];
    const int tid = threadIdx.x, lane = tid & 31, warp = tid >> 5;
    const int wm = (warp & 3) * 32, wn = (warp >> 2) * 64;
    const int z = blockIdx.z;
    const int rowBlk = blockIdx.y * 128, colBlk = blockIdx.x * 256;
    const bf16* wh = g_whi + (size_t)z * NN * MM;
    const bf16* wl = g_wlo + (size_t)z * NN * MM;
    const bf16* vh = g_vhi + (size_t)z * MM * DD;
    const bf16* vl = g_vlo + (size_t)z * MM * DD;

    auto issue = [&](int s, int chunk) {
        bf16* st = (bf16*)ds + s * STAGE_T_E;
        const int k0 = chunk * 32;
        {   // A: 128 rows x 32 cols
            int r = tid >> 2, q = (tid & 3) * 8;
            size_t ga = (size_t)(rowBlk + r) * MM + k0 + q;
            cp16(st + r * LDA + q, wh + ga);
            cp16(st + TA_E + r * LDA + q, wl + ga);
        }
#pragma unroll
        for (int i = 0; i < 2; i++) {  // B: 32 k-rows x 256 cols
            int u = tid + 512 * i, r = u >> 5, q = (u & 31) * 8;
            size_t gb = (size_t)(k0 + r) * DD + colBlk + q;
            cp16(st + 2 * TA_E + r * LDBT + q, vh + gb);
            cp16(st + 2 * TA_E + TBT_E + r * LDBT + q, vl + gb);
        }
    };

    float acc[2][8][4] = {};
    issue(0, 0); CP_COMMIT();
    issue(1, 1); CP_COMMIT();
    for (int it = 0; it < 64; it++) {
        CP_WAIT1();
        __syncthreads();
        if (it + 2 < 64) issue((it + 2) % 3, it + 2);
        CP_COMMIT();
        compute_t((bf16*)ds + (it % 3) * STAGE_T_E, wm, wn, lane, acc);
    }

    float* Og = O + (size_t)z * NN * DD;
#pragma unroll
    for (int mt = 0; mt < 2; mt++)
#pragma unroll
        for (int nt = 0; nt < 8; nt++) {
            int r = rowBlk + wm + mt * 16 + (lane >> 2);
            int c = colBlk + wn + nt * 8 + (lane & 3) * 2;
            float2 v0; v0.x = acc[mt][nt][0]; v0.y = acc[mt][nt][1];
            *(float2*)(Og + (size_t)r * DD + c) = v0;
            float2 v1; v1.x = acc[mt][nt][2]; v1.y = acc[mt][nt][3];
            *(float2*)(Og + (size_t)(r + 8) * DD + c) = v1;
        }
}

// ---------------------------------------------------------------------------
// split: fp32 [rows,1024] -> hi/lo bf16 arrays
// ---------------------------------------------------------------------------
template <int SEL>
__global__ __launch_bounds__(256, 4) void split_k(const float* __restrict__ X) {
    bf16 *H, *L;
    if constexpr (SEL == 0) { H = g_xqh; L = g_xql; }
    else if constexpr (SEL == 1) { H = g_xkh; L = g_xkl; }
    else if constexpr (SEL == 2) { H = g_xvh; L = g_xvl; }
    else if constexpr (SEL == 3) { H = g_wqh; L = g_wql; }
    else if constexpr (SEL == 4) { H = g_wkh; L = g_wkl; }
    else { H = g_wvh; L = g_wvl; }
    size_t row = blockIdx.x;
    int t = threadIdx.x;
    float4 v = ((const float4*)(X + row * 1024))[t];
    bf16 h0, l0, h1, l1, h2, l2, h3, l3;
    split1(v.x, h0, l0); split1(v.y, h1, l1);
    split1(v.z, h2, l2); split1(v.w, h3, l3);
    bf16* ph = H + row * 1024 + t * 4;
    bf16* pl = L + row * 1024 + t * 4;
    *(__nv_bfloat162*)(ph)     = __halves2bfloat162(h0, h1);
    *(__nv_bfloat162*)(ph + 2) = __halves2bfloat162(h2, h3);
    *(__nv_bfloat162*)(pl)     = __halves2bfloat162(l0, l1);
    *(__nv_bfloat162*)(pl + 2) = __halves2bfloat162(l2, l3);
}

// ---------------------------------------------------------------------------
// softmax: scores row -> weights hi/lo
// ---------------------------------------------------------------------------
__global__ __launch_bounds__(256, 1) void softmax_kernel() {
    const int row = blockIdx.x;
    const int tid = threadIdx.x, lane = tid & 31, warp = tid >> 5;
    const float4* S4 = (const float4*)(g_scores + (size_t)row * MM);
    float4 u0 = S4[tid * 2], u1 = S4[tid * 2 + 1];
    float x[8] = {u0.x, u0.y, u0.z, u0.w, u1.x, u1.y, u1.z, u1.w};

    float mx = x[0];
#pragma unroll
    for (int i = 1; i < 8; i++) mx = fmaxf(mx, x[i]);
#pragma unroll
    for (int o = 16; o; o >>= 1) mx = fmaxf(mx, __shfl_xor_sync(0xffffffffu, mx, o));
    __shared__ float redm[8], reds[8];
    if (lane == 0) redm[warp] = mx;
    __syncthreads();
    mx = redm[0];
#pragma unroll
    for (int i = 1; i < 8; i++) mx = fmaxf(mx, redm[i]);

    float e[8], s = 0.f;
#pragma unroll
    for (int i = 0; i < 8; i++) { e[i] = __expf(x[i] - mx); s += e[i]; }
#pragma unroll
    for (int o = 16; o; o >>= 1) s += __shfl_xor_sync(0xffffffffu, s, o);
    if (lane == 0) reds[warp] = s;
    __syncthreads();
    s = reds[0];
#pragma unroll
    for (int i = 1; i < 8; i++) s += reds[i];
    float inv = 1.0f / s;

    bf16 h[8], l[8];
#pragma unroll
    for (int i = 0; i < 8; i++) split1(e[i] * inv, h[i], l[i]);
    uint4 uh, ul;
    __nv_bfloat162* ph = reinterpret_cast<__nv_bfloat162*>(&uh);
    __nv_bfloat162* pl = reinterpret_cast<__nv_bfloat162*>(&ul);
    ph[0] = __halves2bfloat162(h[0], h[1]); ph[1] = __halves2bfloat162(h[2], h[3]);
    ph[2] = __halves2bfloat162(h[4], h[5]); ph[3] = __halves2bfloat162(h[6], h[7]);
    pl[0] = __halves2bfloat162(l[0], l[1]); pl[1] = __halves2bfloat162(l[2], l[3]);
    pl[2] = __halves2bfloat162(l[4], l[5]); pl[3] = __halves2bfloat162(l[6], l[7]);
    *(uint4*)(g_whi + (size_t)row * MM + tid * 8) = uh;
    *(uint4*)(g_wlo + (size_t)row * MM + tid * 8) = ul;
}

// ---------------------------------------------------------------------------
// Launch
// ---------------------------------------------------------------------------
extern "C" void kernel_launch(void* const* d_in, const int* in_sizes, int n_in,
                              void* d_out, int out_size) {
    (void)in_sizes; (void)n_in; (void)out_size;
    const float* querys = (const float*)d_in[0];
    const float* keys   = (const float*)d_in[1];
    const float* values = (const float*)d_in[2];
    const int*   mask   = (const int*)d_in[3];
    const float* Wq     = (const float*)d_in[4];
    const float* bq     = (const float*)d_in[5];
    const float* Wk     = (const float*)d_in[6];
    const float* bk     = (const float*)d_in[7];
    const float* Wv     = (const float*)d_in[8];
    const float* bv     = (const float*)d_in[9];
    float* out = (float*)d_out;

    static bool attr_done = false;
    if (!attr_done) {
        cudaFuncSetAttribute(gemm512<0, 0>, cudaFuncAttributeMaxDynamicSharedMemorySize, SMEM_NT);
        cudaFuncSetAttribute(gemm512<0, 1>, cudaFuncAttributeMaxDynamicSharedMemorySize, SMEM_NT);
        cudaFuncSetAttribute(gemm512<0, 2>, cudaFuncAttributeMaxDynamicSharedMemorySize, SMEM_NT);
        cudaFuncSetAttribute(gemm512<1, 3>, cudaFuncAttributeMaxDynamicSharedMemorySize, SMEM_NT);
        cudaFuncSetAttribute(out512, cudaFuncAttributeMaxDynamicSharedMemorySize, SMEM_T);
        attr_done = true;
    }

    dim3 b256(256), b512(512);
    split_k<0><<<16384, b256>>>(querys);
    split_k<1><<<16384, b256>>>(keys);
    split_k<2><<<16384, b256>>>(values);
    split_k<3><<<1024, b256>>>(Wq);
    split_k<4><<<1024, b256>>>(Wk);
    split_k<5><<<1024, b256>>>(Wv);

    gemm512<0, 0><<<dim3(4, 128, 1), b512, SMEM_NT>>>(bq, nullptr);
    gemm512<0, 1><<<dim3(4, 128, 1), b512, SMEM_NT>>>(bk, nullptr);
    gemm512<0, 2><<<dim3(4, 128, 1), b512, SMEM_NT>>>(bv, nullptr);

    gemm512<1, 3><<<dim3(8, 16, 8), b512, SMEM_NT>>>(nullptr, mask);

    softmax_kernel<<<16384, b256>>>();

    out512<<<dim3(4, 16, 8), b512, SMEM_T>>>(out);
}

// round 7
// speedup vs baseline: 1.6827x; 1.0966x over previous
#include <cuda_runtime.h>
#include <cuda_bf16.h>
#include <cstdint>
#include <cstddef>

// ============================================================================
// Attention_5480378270188 — bf16 hi/lo 3-term mma.sync
// k64 chunks, 2-stage cp.async ring, one barrier per chunk (wait BEFORE sync),
// merged projections
// ============================================================================

#define DEV_INLINE __device__ __forceinline__
typedef __nv_bfloat16 bf16;

constexpr int NN = 2048;
constexpr int MM = 2048;
constexpr int DD = 1024;
constexpr float NEG = -1000000000.0f;

constexpr size_t QKV_ELEMS = (size_t)8 * 2048 * 1024;
constexpr size_t SCORE_ELEMS = (size_t)8 * 2048 * 2048;

// ---------------- device scratch --------------------------------------------
__device__ bf16 g_xqh[QKV_ELEMS], g_xql[QKV_ELEMS];
__device__ bf16 g_xkh[QKV_ELEMS], g_xkl[QKV_ELEMS];
__device__ bf16 g_xvh[QKV_ELEMS], g_xvl[QKV_ELEMS];
__device__ bf16 g_wqh[1024 * 1024], g_wql[1024 * 1024];
__device__ bf16 g_wkh[1024 * 1024], g_wkl[1024 * 1024];
__device__ bf16 g_wvh[1024 * 1024], g_wvl[1024 * 1024];
__device__ bf16 g_qhi[QKV_ELEMS], g_qlo[QKV_ELEMS];
__device__ bf16 g_khi[QKV_ELEMS], g_klo[QKV_ELEMS];
__device__ bf16 g_vhi[QKV_ELEMS], g_vlo[QKV_ELEMS];
__device__ float g_scores[SCORE_ELEMS];
__device__ bf16 g_whi[SCORE_ELEMS], g_wlo[SCORE_ELEMS];

#define LDA64 72    // k64 K-major tiles: rows x (64+8) bf16, 144B rows
#define LDBT  264   // out-kernel B tile: 64 x (256+8) bf16, 528B rows

// ---------------- PTX helpers -----------------------------------------------
DEV_INLINE uint32_t smem_u32(const void* p) { return (uint32_t)__cvta_generic_to_shared(p); }

DEV_INLINE void cp16(void* dst, const void* src) {
    uint32_t d = smem_u32(dst);
    asm volatile("cp.async.cg.shared.global [%0], [%1], 16;\n"
                 :: "r"(d), "l"(__cvta_generic_to_global(src)) : "memory");
}
#define CP_COMMIT() asm volatile("cp.async.commit_group;\n" ::: "memory")
#define CP_WAIT0()  asm volatile("cp.async.wait_group 0;\n" ::: "memory")

DEV_INLINE void ldsm4(uint32_t r[4], const void* p) {
    uint32_t a = smem_u32(p);
    asm volatile("ldmatrix.sync.aligned.m8n8.x4.shared.b16 {%0,%1,%2,%3}, [%4];\n"
                 : "=r"(r[0]), "=r"(r[1]), "=r"(r[2]), "=r"(r[3]) : "r"(a));
}
DEV_INLINE void ldsm4t(uint32_t r[4], const void* p) {
    uint32_t a = smem_u32(p);
    asm volatile("ldmatrix.sync.aligned.m8n8.x4.trans.shared.b16 {%0,%1,%2,%3}, [%4];\n"
                 : "=r"(r[0]), "=r"(r[1]), "=r"(r[2]), "=r"(r[3]) : "r"(a));
}
DEV_INLINE void mma16816(float c[4], const uint32_t a[4], uint32_t b0, uint32_t b1) {
    asm volatile(
        "mma.sync.aligned.m16n8k16.row.col.f32.bf16.bf16.f32 "
        "{%0,%1,%2,%3},{%4,%5,%6,%7},{%8,%9},{%0,%1,%2,%3};\n"
        : "+f"(c[0]), "+f"(c[1]), "+f"(c[2]), "+f"(c[3])
        : "r"(a[0]), "r"(a[1]), "r"(a[2]), "r"(a[3]), "r"(b0), "r"(b1));
}
DEV_INLINE void split1(float v, bf16& h, bf16& l) {
    h = __float2bfloat16(v);
    l = __float2bfloat16(v - __bfloat162float(h));
}

// ---------------- stage layout constants (elements) --------------------------
constexpr int TA64 = 128 * LDA64;                   // 9216
constexpr int TB64 = 256 * LDA64;                   // 18432
constexpr int STAGE_NT_E = 2 * TA64 + 2 * TB64;     // 55296
constexpr int SMEM_NT = 2 * STAGE_NT_E * 2;         // 221184 B

constexpr int TBT64 = 64 * LDBT;                    // 16896
constexpr int STAGE_T_E = 2 * TA64 + 2 * TBT64;     // 52224
constexpr int SMEM_T = 2 * STAGE_T_E * 2;           // 208896 B

// ---------------- compute cores (k64) ----------------------------------------
DEV_INLINE void compute_nt64(const bf16* st, int wm, int wn, int lane,
                             float (&acc)[2][8][4]) {
    const bf16* sAh = st;
    const bf16* sAl = st + TA64;
    const bf16* sBh = st + 2 * TA64;
    const bf16* sBl = st + 2 * TA64 + TB64;
#pragma unroll
    for (int kk = 0; kk < 64; kk += 16) {
        uint32_t ah[2][4], al[2][4], b[4][4];
        const int ar = (lane & 15), ac = kk + (lane >> 4) * 8;
#pragma unroll
        for (int mt = 0; mt < 2; mt++) {
            int r = wm + mt * 16 + ar;
            ldsm4(ah[mt], sAh + r * LDA64 + ac);
            ldsm4(al[mt], sAl + r * LDA64 + ac);
        }
        const int br0 = (lane >> 4) * 8 + (lane & 7);
        const int bc = kk + ((lane >> 3) & 1) * 8;
#pragma unroll
        for (int p = 0; p < 4; p++)
            ldsm4(b[p], sBh + (wn + p * 16 + br0) * LDA64 + bc);
#pragma unroll
        for (int mt = 0; mt < 2; mt++)
#pragma unroll
            for (int p = 0; p < 4; p++) {
                mma16816(acc[mt][2 * p],     ah[mt], b[p][0], b[p][1]);
                mma16816(acc[mt][2 * p + 1], ah[mt], b[p][2], b[p][3]);
                mma16816(acc[mt][2 * p],     al[mt], b[p][0], b[p][1]);
                mma16816(acc[mt][2 * p + 1], al[mt], b[p][2], b[p][3]);
            }
#pragma unroll
        for (int p = 0; p < 4; p++)
            ldsm4(b[p], sBl + (wn + p * 16 + br0) * LDA64 + bc);
#pragma unroll
        for (int mt = 0; mt < 2; mt++)
#pragma unroll
            for (int p = 0; p < 4; p++) {
                mma16816(acc[mt][2 * p],     ah[mt], b[p][0], b[p][1]);
                mma16816(acc[mt][2 * p + 1], ah[mt], b[p][2], b[p][3]);
            }
    }
}

DEV_INLINE void compute_t64(const bf16* st, int wm, int wn, int lane,
                            float (&acc)[2][8][4]) {
    const bf16* sAh = st;
    const bf16* sAl = st + TA64;
    const bf16* sBh = st + 2 * TA64;
    const bf16* sBl = st + 2 * TA64 + TBT64;
#pragma unroll
    for (int kk = 0; kk < 64; kk += 16) {
        uint32_t ah[2][4], al[2][4], b[4][4];
        const int ar = (lane & 15), ac = kk + (lane >> 4) * 8;
#pragma unroll
        for (int mt = 0; mt < 2; mt++) {
            int r = wm + mt * 16 + ar;
            ldsm4(ah[mt], sAh + r * LDA64 + ac);
            ldsm4(al[mt], sAl + r * LDA64 + ac);
        }
        const int br = kk + ((lane >> 3) & 1) * 8 + (lane & 7);
        const int bc0 = wn + (lane >> 4) * 8;
#pragma unroll
        for (int p = 0; p < 4; p++)
            ldsm4t(b[p], sBh + br * LDBT + bc0 + p * 16);
#pragma unroll
        for (int mt = 0; mt < 2; mt++)
#pragma unroll
            for (int p = 0; p < 4; p++) {
                mma16816(acc[mt][2 * p],     ah[mt], b[p][0], b[p][1]);
                mma16816(acc[mt][2 * p + 1], ah[mt], b[p][2], b[p][3]);
                mma16816(acc[mt][2 * p],     al[mt], b[p][0], b[p][1]);
                mma16816(acc[mt][2 * p + 1], al[mt], b[p][2], b[p][3]);
            }
#pragma unroll
        for (int p = 0; p < 4; p++)
            ldsm4t(b[p], sBl + br * LDBT + bc0 + p * 16);
#pragma unroll
        for (int mt = 0; mt < 2; mt++)
#pragma unroll
            for (int p = 0; p < 4; p++) {
                mma16816(acc[mt][2 * p],     ah[mt], b[p][0], b[p][1]);
                mma16816(acc[mt][2 * p + 1], ah[mt], b[p][2], b[p][3]);
            }
    }
}

// ---------------------------------------------------------------------------
// merged projection kernel: grid (4, 128, 3); z selects q/k/v
// ---------------------------------------------------------------------------
__global__ __launch_bounds__(512, 1) void proj3(const float* __restrict__ bq,
                                                const float* __restrict__ bk,
                                                const float* __restrict__ bv) {
    extern __shared__ char ds[];
    const int tid = threadIdx.x, lane = tid & 31, warp = tid >> 5;
    const int wm = (warp & 3) * 32, wn = (warp >> 2) * 64;
    const int rowBlk = blockIdx.y * 128, colBlk = blockIdx.x * 256;
    const int z = blockIdx.z;

    const bf16 *Ah, *Al, *Bh, *Bl;
    bf16 *Chi, *Clo;
    const float* bias;
    if (z == 0)      { Ah = g_xqh; Al = g_xql; Bh = g_wqh; Bl = g_wql; Chi = g_qhi; Clo = g_qlo; bias = bq; }
    else if (z == 1) { Ah = g_xkh; Al = g_xkl; Bh = g_wkh; Bl = g_wkl; Chi = g_khi; Clo = g_klo; bias = bk; }
    else             { Ah = g_xvh; Al = g_xvl; Bh = g_wvh; Bl = g_wvl; Chi = g_vhi; Clo = g_vlo; bias = bv; }

    auto issue = [&](int s, int chunk) {
        bf16* st = (bf16*)ds + s * STAGE_NT_E;
        const int k0 = chunk * 64;
#pragma unroll
        for (int i = 0; i < 2; i++) {   // A: 128 rows x 8 vec16
            int u = tid + 512 * i, r = u >> 3, q = (u & 7) * 8;
            size_t ga = (size_t)(rowBlk + r) * 1024 + k0 + q;
            cp16(st + r * LDA64 + q, Ah + ga);
            cp16(st + TA64 + r * LDA64 + q, Al + ga);
        }
#pragma unroll
        for (int i = 0; i < 4; i++) {   // B: 256 rows x 8 vec16
            int u = tid + 512 * i, r = u >> 3, q = (u & 7) * 8;
            size_t gb = (size_t)(colBlk + r) * 1024 + k0 + q;
            cp16(st + 2 * TA64 + r * LDA64 + q, Bh + gb);
            cp16(st + 2 * TA64 + TB64 + r * LDA64 + q, Bl + gb);
        }
    };

    float acc[2][8][4] = {};
    issue(0, 0); CP_COMMIT();
    for (int it = 0; it < 16; it++) {
        CP_WAIT0();            // my copies for chunk it landed
        __syncthreads();       // everyone's copies visible; compute(it-1) done by all
        if (it + 1 < 16) { issue((it + 1) & 1, it + 1); CP_COMMIT(); }
        compute_nt64((bf16*)ds + (it & 1) * STAGE_NT_E, wm, wn, lane, acc);
    }

#pragma unroll
    for (int mt = 0; mt < 2; mt++)
#pragma unroll
        for (int nt = 0; nt < 8; nt++) {
            int r = rowBlk + wm + mt * 16 + (lane >> 2);
            int c = colBlk + wn + nt * 8 + (lane & 3) * 2;
            float b0 = bias[c], b1 = bias[c + 1];
            {
                bf16 h0, l0, h1, l1;
                split1(acc[mt][nt][0] + b0, h0, l0);
                split1(acc[mt][nt][1] + b1, h1, l1);
                *(__nv_bfloat162*)(Chi + (size_t)r * 1024 + c) = __halves2bfloat162(h0, h1);
                *(__nv_bfloat162*)(Clo + (size_t)r * 1024 + c) = __halves2bfloat162(l0, l1);
            }
            {
                bf16 h0, l0, h1, l1;
                split1(acc[mt][nt][2] + b0, h0, l0);
                split1(acc[mt][nt][3] + b1, h1, l1);
                *(__nv_bfloat162*)(Chi + (size_t)(r + 8) * 1024 + c) = __halves2bfloat162(h0, h1);
                *(__nv_bfloat162*)(Clo + (size_t)(r + 8) * 1024 + c) = __halves2bfloat162(l0, l1);
            }
        }
}

// ---------------------------------------------------------------------------
// score kernel: grid (8, 16, 8); z = batch. S = q·k^T masked -> fp32
// ---------------------------------------------------------------------------
__global__ __launch_bounds__(512, 1) void score512(const int* __restrict__ mask) {
    extern __shared__ char ds[];
    const int tid = threadIdx.x, lane = tid & 31, warp = tid >> 5;
    const int wm = (warp & 3) * 32, wn = (warp >> 2) * 64;
    const int rowBlk = blockIdx.y * 128, colBlk = blockIdx.x * 256;
    const int z = blockIdx.z;
    const size_t zoff = (size_t)z * 2048 * 1024;
    const bf16* Ahp = g_qhi + zoff;  const bf16* Alp = g_qlo + zoff;
    const bf16* Bhp = g_khi + zoff;  const bf16* Blp = g_klo + zoff;

    auto issue = [&](int s, int chunk) {
        bf16* st = (bf16*)ds + s * STAGE_NT_E;
        const int k0 = chunk * 64;
#pragma unroll
        for (int i = 0; i < 2; i++) {
            int u = tid + 512 * i, r = u >> 3, q = (u & 7) * 8;
            size_t ga = (size_t)(rowBlk + r) * 1024 + k0 + q;
            cp16(st + r * LDA64 + q, Ahp + ga);
            cp16(st + TA64 + r * LDA64 + q, Alp + ga);
        }
#pragma unroll
        for (int i = 0; i < 4; i++) {
            int u = tid + 512 * i, r = u >> 3, q = (u & 7) * 8;
            size_t gb = (size_t)(colBlk + r) * 1024 + k0 + q;
            cp16(st + 2 * TA64 + r * LDA64 + q, Bhp + gb);
            cp16(st + 2 * TA64 + TB64 + r * LDA64 + q, Blp + gb);
        }
    };

    float acc[2][8][4] = {};
    issue(0, 0); CP_COMMIT();
    for (int it = 0; it < 16; it++) {
        CP_WAIT0();
        __syncthreads();
        if (it + 1 < 16) { issue((it + 1) & 1, it + 1); CP_COMMIT(); }
        compute_nt64((bf16*)ds + (it & 1) * STAGE_NT_E, wm, wn, lane, acc);
    }

    float* Sg = g_scores + (size_t)z * NN * MM;
#pragma unroll
    for (int mt = 0; mt < 2; mt++)
#pragma unroll
        for (int nt = 0; nt < 8; nt++) {
            int r = rowBlk + wm + mt * 16 + (lane >> 2);
            int c = colBlk + wn + nt * 8 + (lane & 3) * 2;
            {
                int m0 = mask[(size_t)r * MM + c], m1 = mask[(size_t)r * MM + c + 1];
                float2 v;
                v.x = m0 ? acc[mt][nt][0] : NEG;
                v.y = m1 ? acc[mt][nt][1] : NEG;
                *(float2*)(Sg + (size_t)r * MM + c) = v;
            }
            {
                int rr = r + 8;
                int m0 = mask[(size_t)rr * MM + c], m1 = mask[(size_t)rr * MM + c + 1];
                float2 v;
                v.x = m0 ? acc[mt][nt][2] : NEG;
                v.y = m1 ? acc[mt][nt][3] : NEG;
                *(float2*)(Sg + (size_t)rr * MM + c) = v;
            }
        }
}

// ---------------------------------------------------------------------------
// out kernel: grid (4, 16, 8). O = w·v, B via ldmatrix.trans, K=2048
// ---------------------------------------------------------------------------
__global__ __launch_bounds__(512, 1) void out512(float* __restrict__ O) {
    extern __shared__ char ds[];
    const int tid = threadIdx.x, lane = tid & 31, warp = tid >> 5;
    const int wm = (warp & 3) * 32, wn = (warp >> 2) * 64;
    const int z = blockIdx.z;
    const int rowBlk = blockIdx.y * 128, colBlk = blockIdx.x * 256;
    const bf16* wh = g_whi + (size_t)z * NN * MM;
    const bf16* wl = g_wlo + (size_t)z * NN * MM;
    const bf16* vh = g_vhi + (size_t)z * MM * DD;
    const bf16* vl = g_vlo + (size_t)z * MM * DD;

    auto issue = [&](int s, int chunk) {
        bf16* st = (bf16*)ds + s * STAGE_T_E;
        const int k0 = chunk * 64;
#pragma unroll
        for (int i = 0; i < 2; i++) {   // A: 128 rows x 8 vec16
            int u = tid + 512 * i, r = u >> 3, q = (u & 7) * 8;
            size_t ga = (size_t)(rowBlk + r) * MM + k0 + q;
            cp16(st + r * LDA64 + q, wh + ga);
            cp16(st + TA64 + r * LDA64 + q, wl + ga);
        }
#pragma unroll
        for (int i = 0; i < 4; i++) {   // B: 64 k-rows x 32 vec16
            int u = tid + 512 * i, r = u >> 5, q = (u & 31) * 8;
            size_t gb = (size_t)(k0 + r) * DD + colBlk + q;
            cp16(st + 2 * TA64 + r * LDBT + q, vh + gb);
            cp16(st + 2 * TA64 + TBT64 + r * LDBT + q, vl + gb);
        }
    };

    float acc[2][8][4] = {};
    issue(0, 0); CP_COMMIT();
    for (int it = 0; it < 32; it++) {
        CP_WAIT0();
        __syncthreads();
        if (it + 1 < 32) { issue((it + 1) & 1, it + 1); CP_COMMIT(); }
        compute_t64((bf16*)ds + (it & 1) * STAGE_T_E, wm, wn, lane, acc);
    }

    float* Og = O + (size_t)z * NN * DD;
#pragma unroll
    for (int mt = 0; mt < 2; mt++)
#pragma unroll
        for (int nt = 0; nt < 8; nt++) {
            int r = rowBlk + wm + mt * 16 + (lane >> 2);
            int c = colBlk + wn + nt * 8 + (lane & 3) * 2;
            float2 v0; v0.x = acc[mt][nt][0]; v0.y = acc[mt][nt][1];
            *(float2*)(Og + (size_t)r * DD + c) = v0;
            float2 v1; v1.x = acc[mt][nt][2]; v1.y = acc[mt][nt][3];
            *(float2*)(Og + (size_t)(r + 8) * DD + c) = v1;
        }
}

// ---------------------------------------------------------------------------
// split: fp32 [rows,1024] -> hi/lo bf16 arrays
// ---------------------------------------------------------------------------
template <int SEL>
__global__ __launch_bounds__(256, 4) void split_k(const float* __restrict__ X) {
    bf16 *H, *L;
    if constexpr (SEL == 0) { H = g_xqh; L = g_xql; }
    else if constexpr (SEL == 1) { H = g_xkh; L = g_xkl; }
    else if constexpr (SEL == 2) { H = g_xvh; L = g_xvl; }
    else if constexpr (SEL == 3) { H = g_wqh; L = g_wql; }
    else if constexpr (SEL == 4) { H = g_wkh; L = g_wkl; }
    else { H = g_wvh; L = g_wvl; }
    size_t row = blockIdx.x;
    int t = threadIdx.x;
    float4 v = ((const float4*)(X + row * 1024))[t];
    bf16 h0, l0, h1, l1, h2, l2, h3, l3;
    split1(v.x, h0, l0); split1(v.y, h1, l1);
    split1(v.z, h2, l2); split1(v.w, h3, l3);
    bf16* ph = H + row * 1024 + t * 4;
    bf16* pl = L + row * 1024 + t * 4;
    *(__nv_bfloat162*)(ph)     = __halves2bfloat162(h0, h1);
    *(__nv_bfloat162*)(ph + 2) = __halves2bfloat162(h2, h3);
    *(__nv_bfloat162*)(pl)     = __halves2bfloat162(l0, l1);
    *(__nv_bfloat162*)(pl + 2) = __halves2bfloat162(l2, l3);
}

// ---------------------------------------------------------------------------
// softmax: scores row -> weights hi/lo
// ---------------------------------------------------------------------------
__global__ __launch_bounds__(256, 1) void softmax_kernel() {
    const int row = blockIdx.x;
    const int tid = threadIdx.x, lane = tid & 31, warp = tid >> 5;
    const float4* S4 = (const float4*)(g_scores + (size_t)row * MM);
    float4 u0 = S4[tid * 2], u1 = S4[tid * 2 + 1];
    float x[8] = {u0.x, u0.y, u0.z, u0.w, u1.x, u1.y, u1.z, u1.w};

    float mx = x[0];
#pragma unroll
    for (int i = 1; i < 8; i++) mx = fmaxf(mx, x[i]);
#pragma unroll
    for (int o = 16; o; o >>= 1) mx = fmaxf(mx, __shfl_xor_sync(0xffffffffu, mx, o));
    __shared__ float redm[8], reds[8];
    if (lane == 0) redm[warp] = mx;
    __syncthreads();
    mx = redm[0];
#pragma unroll
    for (int i = 1; i < 8; i++) mx = fmaxf(mx, redm[i]);

    float e[8], s = 0.f;
#pragma unroll
    for (int i = 0; i < 8; i++) { e[i] = __expf(x[i] - mx); s += e[i]; }
#pragma unroll
    for (int o = 16; o; o >>= 1) s += __shfl_xor_sync(0xffffffffu, s, o);
    if (lane == 0) reds[warp] = s;
    __syncthreads();
    s = reds[0];
#pragma unroll
    for (int i = 1; i < 8; i++) s += reds[i];
    float inv = 1.0f / s;

    bf16 h[8], l[8];
#pragma unroll
    for (int i = 0; i < 8; i++) split1(e[i] * inv, h[i], l[i]);
    uint4 uh, ul;
    __nv_bfloat162* ph = reinterpret_cast<__nv_bfloat162*>(&uh);
    __nv_bfloat162* pl = reinterpret_cast<__nv_bfloat162*>(&ul);
    ph[0] = __halves2bfloat162(h[0], h[1]); ph[1] = __halves2bfloat162(h[2], h[3]);
    ph[2] = __halves2bfloat162(h[4], h[5]); ph[3] = __halves2bfloat162(h[6], h[7]);
    pl[0] = __halves2bfloat162(l[0], l[1]); pl[1] = __halves2bfloat162(l[2], l[3]);
    pl[2] = __halves2bfloat162(l[4], l[5]); pl[3] = __halves2bfloat162(l[6], l[7]);
    *(uint4*)(g_whi + (size_t)row * MM + tid * 8) = uh;
    *(uint4*)(g_wlo + (size_t)row * MM + tid * 8) = ul;
}

// ---------------------------------------------------------------------------
// Launch
// ---------------------------------------------------------------------------
extern "C" void kernel_launch(void* const* d_in, const int* in_sizes, int n_in,
                              void* d_out, int out_size) {
    (void)in_sizes; (void)n_in; (void)out_size;
    const float* querys = (const float*)d_in[0];
    const float* keys   = (const float*)d_in[1];
    const float* values = (const float*)d_in[2];
    const int*   mask   = (const int*)d_in[3];
    const float* Wq     = (const float*)d_in[4];
    const float* bq     = (const float*)d_in[5];
    const float* Wk     = (const float*)d_in[6];
    const float* bk     = (const float*)d_in[7];
    const float* Wv     = (const float*)d_in[8];
    const float* bv     = (const float*)d_in[9];
    float* out = (float*)d_out;

    static bool attr_done = false;
    if (!attr_done) {
        cudaFuncSetAttribute(proj3, cudaFuncAttributeMaxDynamicSharedMemorySize, SMEM_NT);
        cudaFuncSetAttribute(score512, cudaFuncAttributeMaxDynamicSharedMemorySize, SMEM_NT);
        cudaFuncSetAttribute(out512, cudaFuncAttributeMaxDynamicSharedMemorySize, SMEM_T);
        attr_done = true;
    }

    dim3 b256(256), b512(512);
    split_k<0><<<16384, b256>>>(querys);
    split_k<1><<<16384, b256>>>(keys);
    split_k<2><<<16384, b256>>>(values);
    split_k<3><<<1024, b256>>>(Wq);
    split_k<4><<<1024, b256>>>(Wk);
    split_k<5><<<1024, b256>>>(Wv);

    proj3<<<dim3(4, 128, 3), b512, SMEM_NT>>>(bq, bk, bv);

    score512<<<dim3(8, 16, 8), b512, SMEM_NT>>>(mask);

    softmax_kernel<<<16384, b256>>>();

    out512<<<dim3(4, 16, 8), b512, SMEM_T>>>(out);
}

// round 8
// speedup vs baseline: 1.7041x; 1.0127x over previous
#include <cuda_runtime.h>
#include <cuda_bf16.h>
#include <cstdint>
#include <cstddef>

// ============================================================================
// Attention_5480378270188 — bf16 hi/lo 3-term mma.sync
// k64 chunks, 2-stage cp.async ring, one barrier/chunk, warp tile 64m x 32n
// ============================================================================

#define DEV_INLINE __device__ __forceinline__
typedef __nv_bfloat16 bf16;

constexpr int NN = 2048;
constexpr int MM = 2048;
constexpr int DD = 1024;
constexpr float NEG = -1000000000.0f;

constexpr size_t QKV_ELEMS = (size_t)8 * 2048 * 1024;
constexpr size_t SCORE_ELEMS = (size_t)8 * 2048 * 2048;

// ---------------- device scratch --------------------------------------------
__device__ bf16 g_xqh[QKV_ELEMS], g_xql[QKV_ELEMS];
__device__ bf16 g_xkh[QKV_ELEMS], g_xkl[QKV_ELEMS];
__device__ bf16 g_xvh[QKV_ELEMS], g_xvl[QKV_ELEMS];
__device__ bf16 g_wqh[1024 * 1024], g_wql[1024 * 1024];
__device__ bf16 g_wkh[1024 * 1024], g_wkl[1024 * 1024];
__device__ bf16 g_wvh[1024 * 1024], g_wvl[1024 * 1024];
__device__ bf16 g_qhi[QKV_ELEMS], g_qlo[QKV_ELEMS];
__device__ bf16 g_khi[QKV_ELEMS], g_klo[QKV_ELEMS];
__device__ bf16 g_vhi[QKV_ELEMS], g_vlo[QKV_ELEMS];
__device__ float g_scores[SCORE_ELEMS];
__device__ bf16 g_whi[SCORE_ELEMS], g_wlo[SCORE_ELEMS];

#define LDA64 72    // k64 K-major tiles: rows x (64+8) bf16, 144B rows
#define LDBT  264   // out-kernel B tile: 64 x (256+8) bf16, 528B rows

// ---------------- PTX helpers -----------------------------------------------
DEV_INLINE uint32_t smem_u32(const void* p) { return (uint32_t)__cvta_generic_to_shared(p); }

DEV_INLINE void cp16(void* dst, const void* src) {
    uint32_t d = smem_u32(dst);
    asm volatile("cp.async.cg.shared.global [%0], [%1], 16;\n"
                 :: "r"(d), "l"(__cvta_generic_to_global(src)) : "memory");
}
#define CP_COMMIT() asm volatile("cp.async.commit_group;\n" ::: "memory")
#define CP_WAIT0()  asm volatile("cp.async.wait_group 0;\n" ::: "memory")

DEV_INLINE void ldsm4(uint32_t r[4], const void* p) {
    uint32_t a = smem_u32(p);
    asm volatile("ldmatrix.sync.aligned.m8n8.x4.shared.b16 {%0,%1,%2,%3}, [%4];\n"
                 : "=r"(r[0]), "=r"(r[1]), "=r"(r[2]), "=r"(r[3]) : "r"(a));
}
DEV_INLINE void ldsm4t(uint32_t r[4], const void* p) {
    uint32_t a = smem_u32(p);
    asm volatile("ldmatrix.sync.aligned.m8n8.x4.trans.shared.b16 {%0,%1,%2,%3}, [%4];\n"
                 : "=r"(r[0]), "=r"(r[1]), "=r"(r[2]), "=r"(r[3]) : "r"(a));
}
DEV_INLINE void mma16816(float c[4], const uint32_t a[4], uint32_t b0, uint32_t b1) {
    asm volatile(
        "mma.sync.aligned.m16n8k16.row.col.f32.bf16.bf16.f32 "
        "{%0,%1,%2,%3},{%4,%5,%6,%7},{%8,%9},{%0,%1,%2,%3};\n"
        : "+f"(c[0]), "+f"(c[1]), "+f"(c[2]), "+f"(c[3])
        : "r"(a[0]), "r"(a[1]), "r"(a[2]), "r"(a[3]), "r"(b0), "r"(b1));
}
DEV_INLINE void split1(float v, bf16& h, bf16& l) {
    h = __float2bfloat16(v);
    l = __float2bfloat16(v - __bfloat162float(h));
}

// ---------------- stage layout constants (elements) --------------------------
constexpr int TA64 = 128 * LDA64;                   // 9216
constexpr int TB64 = 256 * LDA64;                   // 18432
constexpr int STAGE_NT_E = 2 * TA64 + 2 * TB64;     // 55296
constexpr int SMEM_NT = 2 * STAGE_NT_E * 2;         // 221184 B

constexpr int TBT64 = 64 * LDBT;                    // 16896
constexpr int STAGE_T_E = 2 * TA64 + 2 * TBT64;     // 52224
constexpr int SMEM_T = 2 * STAGE_T_E * 2;           // 208896 B

// ---------------- compute cores: warp tile 64m x 32n -------------------------
// acc[4 mt][4 nt][4]; A hi/lo kept in regs across all 3 terms; B regs reused.
DEV_INLINE void compute_nt64(const bf16* st, int wm, int wn, int lane,
                             float (&acc)[4][4][4]) {
    const bf16* sAh = st;
    const bf16* sAl = st + TA64;
    const bf16* sBh = st + 2 * TA64;
    const bf16* sBl = st + 2 * TA64 + TB64;
#pragma unroll
    for (int kk = 0; kk < 64; kk += 16) {
        uint32_t ah[4][4], al[4][4], b[2][4];
        const int ar = (lane & 15), ac = kk + (lane >> 4) * 8;
#pragma unroll
        for (int mt = 0; mt < 4; mt++) {
            int r = wm + mt * 16 + ar;
            ldsm4(ah[mt], sAh + r * LDA64 + ac);
            ldsm4(al[mt], sAl + r * LDA64 + ac);
        }
        const int br0 = (lane >> 4) * 8 + (lane & 7);
        const int bc = kk + ((lane >> 3) & 1) * 8;
#pragma unroll
        for (int p = 0; p < 2; p++)
            ldsm4(b[p], sBh + (wn + p * 16 + br0) * LDA64 + bc);
#pragma unroll
        for (int mt = 0; mt < 4; mt++)
#pragma unroll
            for (int p = 0; p < 2; p++) {
                mma16816(acc[mt][2 * p],     ah[mt], b[p][0], b[p][1]);
                mma16816(acc[mt][2 * p + 1], ah[mt], b[p][2], b[p][3]);
            }
#pragma unroll
        for (int mt = 0; mt < 4; mt++)
#pragma unroll
            for (int p = 0; p < 2; p++) {
                mma16816(acc[mt][2 * p],     al[mt], b[p][0], b[p][1]);
                mma16816(acc[mt][2 * p + 1], al[mt], b[p][2], b[p][3]);
            }
#pragma unroll
        for (int p = 0; p < 2; p++)
            ldsm4(b[p], sBl + (wn + p * 16 + br0) * LDA64 + bc);
#pragma unroll
        for (int mt = 0; mt < 4; mt++)
#pragma unroll
            for (int p = 0; p < 2; p++) {
                mma16816(acc[mt][2 * p],     ah[mt], b[p][0], b[p][1]);
                mma16816(acc[mt][2 * p + 1], ah[mt], b[p][2], b[p][3]);
            }
    }
}

DEV_INLINE void compute_t64(const bf16* st, int wm, int wn, int lane,
                            float (&acc)[4][4][4]) {
    const bf16* sAh = st;
    const bf16* sAl = st + TA64;
    const bf16* sBh = st + 2 * TA64;
    const bf16* sBl = st + 2 * TA64 + TBT64;
#pragma unroll
    for (int kk = 0; kk < 64; kk += 16) {
        uint32_t ah[4][4], al[4][4], b[2][4];
        const int ar = (lane & 15), ac = kk + (lane >> 4) * 8;
#pragma unroll
        for (int mt = 0; mt < 4; mt++) {
            int r = wm + mt * 16 + ar;
            ldsm4(ah[mt], sAh + r * LDA64 + ac);
            ldsm4(al[mt], sAl + r * LDA64 + ac);
        }
        const int br = kk + ((lane >> 3) & 1) * 8 + (lane & 7);
        const int bc0 = wn + (lane >> 4) * 8;
#pragma unroll
        for (int p = 0; p < 2; p++)
            ldsm4t(b[p], sBh + br * LDBT + bc0 + p * 16);
#pragma unroll
        for (int mt = 0; mt < 4; mt++)
#pragma unroll
            for (int p = 0; p < 2; p++) {
                mma16816(acc[mt][2 * p],     ah[mt], b[p][0], b[p][1]);
                mma16816(acc[mt][2 * p + 1], ah[mt], b[p][2], b[p][3]);
            }
#pragma unroll
        for (int mt = 0; mt < 4; mt++)
#pragma unroll
            for (int p = 0; p < 2; p++) {
                mma16816(acc[mt][2 * p],     al[mt], b[p][0], b[p][1]);
                mma16816(acc[mt][2 * p + 1], al[mt], b[p][2], b[p][3]);
            }
#pragma unroll
        for (int p = 0; p < 2; p++)
            ldsm4t(b[p], sBl + br * LDBT + bc0 + p * 16);
#pragma unroll
        for (int mt = 0; mt < 4; mt++)
#pragma unroll
            for (int p = 0; p < 2; p++) {
                mma16816(acc[mt][2 * p],     ah[mt], b[p][0], b[p][1]);
                mma16816(acc[mt][2 * p + 1], ah[mt], b[p][2], b[p][3]);
            }
    }
}

// ---------------------------------------------------------------------------
// merged projection kernel: grid (4, 128, 3); z selects q/k/v
// warp layout: 2(m) x 8(n); wm = (warp&1)*64, wn = (warp>>1)*32
// ---------------------------------------------------------------------------
__global__ __launch_bounds__(512, 1) void proj3(const float* __restrict__ bq,
                                                const float* __restrict__ bk,
                                                const float* __restrict__ bv) {
    extern __shared__ char ds[];
    const int tid = threadIdx.x, lane = tid & 31, warp = tid >> 5;
    const int wm = (warp & 1) * 64, wn = (warp >> 1) * 32;
    const int rowBlk = blockIdx.y * 128, colBlk = blockIdx.x * 256;
    const int z = blockIdx.z;

    const bf16 *Ah, *Al, *Bh, *Bl;
    bf16 *Chi, *Clo;
    const float* bias;
    if (z == 0)      { Ah = g_xqh; Al = g_xql; Bh = g_wqh; Bl = g_wql; Chi = g_qhi; Clo = g_qlo; bias = bq; }
    else if (z == 1) { Ah = g_xkh; Al = g_xkl; Bh = g_wkh; Bl = g_wkl; Chi = g_khi; Clo = g_klo; bias = bk; }
    else             { Ah = g_xvh; Al = g_xvl; Bh = g_wvh; Bl = g_wvl; Chi = g_vhi; Clo = g_vlo; bias = bv; }

    auto issue = [&](int s, int chunk) {
        bf16* st = (bf16*)ds + s * STAGE_NT_E;
        const int k0 = chunk * 64;
#pragma unroll
        for (int i = 0; i < 2; i++) {   // A: 128 rows x 8 vec16
            int u = tid + 512 * i, r = u >> 3, q = (u & 7) * 8;
            size_t ga = (size_t)(rowBlk + r) * 1024 + k0 + q;
            cp16(st + r * LDA64 + q, Ah + ga);
            cp16(st + TA64 + r * LDA64 + q, Al + ga);
        }
#pragma unroll
        for (int i = 0; i < 4; i++) {   // B: 256 rows x 8 vec16
            int u = tid + 512 * i, r = u >> 3, q = (u & 7) * 8;
            size_t gb = (size_t)(colBlk + r) * 1024 + k0 + q;
            cp16(st + 2 * TA64 + r * LDA64 + q, Bh + gb);
            cp16(st + 2 * TA64 + TB64 + r * LDA64 + q, Bl + gb);
        }
    };

    float acc[4][4][4] = {};
    issue(0, 0); CP_COMMIT();
    for (int it = 0; it < 16; it++) {
        CP_WAIT0();            // my copies for chunk it landed
        __syncthreads();       // everyone's copies visible; compute(it-1) done by all
        if (it + 1 < 16) { issue((it + 1) & 1, it + 1); CP_COMMIT(); }
        compute_nt64((bf16*)ds + (it & 1) * STAGE_NT_E, wm, wn, lane, acc);
    }

#pragma unroll
    for (int mt = 0; mt < 4; mt++)
#pragma unroll
        for (int nt = 0; nt < 4; nt++) {
            int r = rowBlk + wm + mt * 16 + (lane >> 2);
            int c = colBlk + wn + nt * 8 + (lane & 3) * 2;
            float b0 = bias[c], b1 = bias[c + 1];
            {
                bf16 h0, l0, h1, l1;
                split1(acc[mt][nt][0] + b0, h0, l0);
                split1(acc[mt][nt][1] + b1, h1, l1);
                *(__nv_bfloat162*)(Chi + (size_t)r * 1024 + c) = __halves2bfloat162(h0, h1);
                *(__nv_bfloat162*)(Clo + (size_t)r * 1024 + c) = __halves2bfloat162(l0, l1);
            }
            {
                bf16 h0, l0, h1, l1;
                split1(acc[mt][nt][2] + b0, h0, l0);
                split1(acc[mt][nt][3] + b1, h1, l1);
                *(__nv_bfloat162*)(Chi + (size_t)(r + 8) * 1024 + c) = __halves2bfloat162(h0, h1);
                *(__nv_bfloat162*)(Clo + (size_t)(r + 8) * 1024 + c) = __halves2bfloat162(l0, l1);
            }
        }
}

// ---------------------------------------------------------------------------
// score kernel: grid (8, 16, 8); z = batch
// ---------------------------------------------------------------------------
__global__ __launch_bounds__(512, 1) void score512(const int* __restrict__ mask) {
    extern __shared__ char ds[];
    const int tid = threadIdx.x, lane = tid & 31, warp = tid >> 5;
    const int wm = (warp & 1) * 64, wn = (warp >> 1) * 32;
    const int rowBlk = blockIdx.y * 128, colBlk = blockIdx.x * 256;
    const int z = blockIdx.z;
    const size_t zoff = (size_t)z * 2048 * 1024;
    const bf16* Ahp = g_qhi + zoff;  const bf16* Alp = g_qlo + zoff;
    const bf16* Bhp = g_khi + zoff;  const bf16* Blp = g_klo + zoff;

    auto issue = [&](int s, int chunk) {
        bf16* st = (bf16*)ds + s * STAGE_NT_E;
        const int k0 = chunk * 64;
#pragma unroll
        for (int i = 0; i < 2; i++) {
            int u = tid + 512 * i, r = u >> 3, q = (u & 7) * 8;
            size_t ga = (size_t)(rowBlk + r) * 1024 + k0 + q;
            cp16(st + r * LDA64 + q, Ahp + ga);
            cp16(st + TA64 + r * LDA64 + q, Alp + ga);
        }
#pragma unroll
        for (int i = 0; i < 4; i++) {
            int u = tid + 512 * i, r = u >> 3, q = (u & 7) * 8;
            size_t gb = (size_t)(colBlk + r) * 1024 + k0 + q;
            cp16(st + 2 * TA64 + r * LDA64 + q, Bhp + gb);
            cp16(st + 2 * TA64 + TB64 + r * LDA64 + q, Blp + gb);
        }
    };

    float acc[4][4][4] = {};
    issue(0, 0); CP_COMMIT();
    for (int it = 0; it < 16; it++) {
        CP_WAIT0();
        __syncthreads();
        if (it + 1 < 16) { issue((it + 1) & 1, it + 1); CP_COMMIT(); }
        compute_nt64((bf16*)ds + (it & 1) * STAGE_NT_E, wm, wn, lane, acc);
    }

    float* Sg = g_scores + (size_t)z * NN * MM;
#pragma unroll
    for (int mt = 0; mt < 4; mt++)
#pragma unroll
        for (int nt = 0; nt < 4; nt++) {
            int r = rowBlk + wm + mt * 16 + (lane >> 2);
            int c = colBlk + wn + nt * 8 + (lane & 3) * 2;
            {
                int m0 = mask[(size_t)r * MM + c], m1 = mask[(size_t)r * MM + c + 1];
                float2 v;
                v.x = m0 ? acc[mt][nt][0] : NEG;
                v.y = m1 ? acc[mt][nt][1] : NEG;
                *(float2*)(Sg + (size_t)r * MM + c) = v;
            }
            {
                int rr = r + 8;
                int m0 = mask[(size_t)rr * MM + c], m1 = mask[(size_t)rr * MM + c + 1];
                float2 v;
                v.x = m0 ? acc[mt][nt][2] : NEG;
                v.y = m1 ? acc[mt][nt][3] : NEG;
                *(float2*)(Sg + (size_t)rr * MM + c) = v;
            }
        }
}

// ---------------------------------------------------------------------------
// out kernel: grid (4, 16, 8). O = w·v, B via ldmatrix.trans, K=2048
// ---------------------------------------------------------------------------
__global__ __launch_bounds__(512, 1) void out512(float* __restrict__ O) {
    extern __shared__ char ds[];
    const int tid = threadIdx.x, lane = tid & 31, warp = tid >> 5;
    const int wm = (warp & 1) * 64, wn = (warp >> 1) * 32;
    const int z = blockIdx.z;
    const int rowBlk = blockIdx.y * 128, colBlk = blockIdx.x * 256;
    const bf16* wh = g_whi + (size_t)z * NN * MM;
    const bf16* wl = g_wlo + (size_t)z * NN * MM;
    const bf16* vh = g_vhi + (size_t)z * MM * DD;
    const bf16* vl = g_vlo + (size_t)z * MM * DD;

    auto issue = [&](int s, int chunk) {
        bf16* st = (bf16*)ds + s * STAGE_T_E;
        const int k0 = chunk * 64;
#pragma unroll
        for (int i = 0; i < 2; i++) {   // A: 128 rows x 8 vec16
            int u = tid + 512 * i, r = u >> 3, q = (u & 7) * 8;
            size_t ga = (size_t)(rowBlk + r) * MM + k0 + q;
            cp16(st + r * LDA64 + q, wh + ga);
            cp16(st + TA64 + r * LDA64 + q, wl + ga);
        }
#pragma unroll
        for (int i = 0; i < 4; i++) {   // B: 64 k-rows x 32 vec16
            int u = tid + 512 * i, r = u >> 5, q = (u & 31) * 8;
            size_t gb = (size_t)(k0 + r) * DD + colBlk + q;
            cp16(st + 2 * TA64 + r * LDBT + q, vh + gb);
            cp16(st + 2 * TA64 + TBT64 + r * LDBT + q, vl + gb);
        }
    };

    float acc[4][4][4] = {};
    issue(0, 0); CP_COMMIT();
    for (int it = 0; it < 32; it++) {
        CP_WAIT0();
        __syncthreads();
        if (it + 1 < 32) { issue((it + 1) & 1, it + 1); CP_COMMIT(); }
        compute_t64((bf16*)ds + (it & 1) * STAGE_T_E, wm, wn, lane, acc);
    }

    float* Og = O + (size_t)z * NN * DD;
#pragma unroll
    for (int mt = 0; mt < 4; mt++)
#pragma unroll
        for (int nt = 0; nt < 4; nt++) {
            int r = rowBlk + wm + mt * 16 + (lane >> 2);
            int c = colBlk + wn + nt * 8 + (lane & 3) * 2;
            float2 v0; v0.x = acc[mt][nt][0]; v0.y = acc[mt][nt][1];
            *(float2*)(Og + (size_t)r * DD + c) = v0;
            float2 v1; v1.x = acc[mt][nt][2]; v1.y = acc[mt][nt][3];
            *(float2*)(Og + (size_t)(r + 8) * DD + c) = v1;
        }
}

// ---------------------------------------------------------------------------
// splits: fp32 [rows,1024] -> hi/lo bf16; merged over q/k/v via grid.z
// ---------------------------------------------------------------------------
__global__ __launch_bounds__(256, 4) void split_in(const float* __restrict__ Xq,
                                                   const float* __restrict__ Xk,
                                                   const float* __restrict__ Xv) {
    const float* X; bf16 *H, *L;
    if (blockIdx.y == 0)      { X = Xq; H = g_xqh; L = g_xql; }
    else if (blockIdx.y == 1) { X = Xk; H = g_xkh; L = g_xkl; }
    else                      { X = Xv; H = g_xvh; L = g_xvl; }
    size_t row = blockIdx.x;
    int t = threadIdx.x;
    float4 v = ((const float4*)(X + row * 1024))[t];
    bf16 h0, l0, h1, l1, h2, l2, h3, l3;
    split1(v.x, h0, l0); split1(v.y, h1, l1);
    split1(v.z, h2, l2); split1(v.w, h3, l3);
    bf16* ph = H + row * 1024 + t * 4;
    bf16* pl = L + row * 1024 + t * 4;
    *(__nv_bfloat162*)(ph)     = __halves2bfloat162(h0, h1);
    *(__nv_bfloat162*)(ph + 2) = __halves2bfloat162(h2, h3);
    *(__nv_bfloat162*)(pl)     = __halves2bfloat162(l0, l1);
    *(__nv_bfloat162*)(pl + 2) = __halves2bfloat162(l2, l3);
}

__global__ __launch_bounds__(256, 4) void split_w(const float* __restrict__ Wq,
                                                  const float* __restrict__ Wk,
                                                  const float* __restrict__ Wv) {
    const float* X; bf16 *H, *L;
    if (blockIdx.y == 0)      { X = Wq; H = g_wqh; L = g_wql; }
    else if (blockIdx.y == 1) { X = Wk; H = g_wkh; L = g_wkl; }
    else                      { X = Wv; H = g_wvh; L = g_wvl; }
    size_t row = blockIdx.x;
    int t = threadIdx.x;
    float4 v = ((const float4*)(X + row * 1024))[t];
    bf16 h0, l0, h1, l1, h2, l2, h3, l3;
    split1(v.x, h0, l0); split1(v.y, h1, l1);
    split1(v.z, h2, l2); split1(v.w, h3, l3);
    bf16* ph = H + row * 1024 + t * 4;
    bf16* pl = L + row * 1024 + t * 4;
    *(__nv_bfloat162*)(ph)     = __halves2bfloat162(h0, h1);
    *(__nv_bfloat162*)(ph + 2) = __halves2bfloat162(h2, h3);
    *(__nv_bfloat162*)(pl)     = __halves2bfloat162(l0, l1);
    *(__nv_bfloat162*)(pl + 2) = __halves2bfloat162(l2, l3);
}

// ---------------------------------------------------------------------------
// softmax: scores row -> weights hi/lo
// ---------------------------------------------------------------------------
__global__ __launch_bounds__(256, 1) void softmax_kernel() {
    const int row = blockIdx.x;
    const int tid = threadIdx.x, lane = tid & 31, warp = tid >> 5;
    const float4* S4 = (const float4*)(g_scores + (size_t)row * MM);
    float4 u0 = S4[tid * 2], u1 = S4[tid * 2 + 1];
    float x[8] = {u0.x, u0.y, u0.z, u0.w, u1.x, u1.y, u1.z, u1.w};

    float mx = x[0];
#pragma unroll
    for (int i = 1; i < 8; i++) mx = fmaxf(mx, x[i]);
#pragma unroll
    for (int o = 16; o; o >>= 1) mx = fmaxf(mx, __shfl_xor_sync(0xffffffffu, mx, o));
    __shared__ float redm[8], reds[8];
    if (lane == 0) redm[warp] = mx;
    __syncthreads();
    mx = redm[0];
#pragma unroll
    for (int i = 1; i < 8; i++) mx = fmaxf(mx, redm[i]);

    float e[8], s = 0.f;
#pragma unroll
    for (int i = 0; i < 8; i++) { e[i] = __expf(x[i] - mx); s += e[i]; }
#pragma unroll
    for (int o = 16; o; o >>= 1) s += __shfl_xor_sync(0xffffffffu, s, o);
    if (lane == 0) reds[warp] = s;
    __syncthreads();
    s = reds[0];
#pragma unroll
    for (int i = 1; i < 8; i++) s += reds[i];
    float inv = 1.0f / s;

    bf16 h[8], l[8];
#pragma unroll
    for (int i = 0; i < 8; i++) split1(e[i] * inv, h[i], l[i]);
    uint4 uh, ul;
    __nv_bfloat162* ph = reinterpret_cast<__nv_bfloat162*>(&uh);
    __nv_bfloat162* pl = reinterpret_cast<__nv_bfloat162*>(&ul);
    ph[0] = __halves2bfloat162(h[0], h[1]); ph[1] = __halves2bfloat162(h[2], h[3]);
    ph[2] = __halves2bfloat162(h[4], h[5]); ph[3] = __halves2bfloat162(h[6], h[7]);
    pl[0] = __halves2bfloat162(l[0], l[1]); pl[1] = __halves2bfloat162(l[2], l[3]);
    pl[2] = __halves2bfloat162(l[4], l[5]); pl[3] = __halves2bfloat162(l[6], l[7]);
    *(uint4*)(g_whi + (size_t)row * MM + tid * 8) = uh;
    *(uint4*)(g_wlo + (size_t)row * MM + tid * 8) = ul;
}

// ---------------------------------------------------------------------------
// Launch
// ---------------------------------------------------------------------------
extern "C" void kernel_launch(void* const* d_in, const int* in_sizes, int n_in,
                              void* d_out, int out_size) {
    (void)in_sizes; (void)n_in; (void)out_size;
    const float* querys = (const float*)d_in[0];
    const float* keys   = (const float*)d_in[1];
    const float* values = (const float*)d_in[2];
    const int*   mask   = (const int*)d_in[3];
    const float* Wq     = (const float*)d_in[4];
    const float* bq     = (const float*)d_in[5];
    const float* Wk     = (const float*)d_in[6];
    const float* bk     = (const float*)d_in[7];
    const float* Wv     = (const float*)d_in[8];
    const float* bv     = (const float*)d_in[9];
    float* out = (float*)d_out;

    static bool attr_done = false;
    if (!attr_done) {
        cudaFuncSetAttribute(proj3, cudaFuncAttributeMaxDynamicSharedMemorySize, SMEM_NT);
        cudaFuncSetAttribute(score512, cudaFuncAttributeMaxDynamicSharedMemorySize, SMEM_NT);
        cudaFuncSetAttribute(out512, cudaFuncAttributeMaxDynamicSharedMemorySize, SMEM_T);
        attr_done = true;
    }

    dim3 b256(256), b512(512);
    split_in<<<dim3(16384, 3), b256>>>(querys, keys, values);
    split_w<<<dim3(1024, 3), b256>>>(Wq, Wk, Wv);

    proj3<<<dim3(4, 128, 3), b512, SMEM_NT>>>(bq, bk, bv);

    score512<<<dim3(8, 16, 8), b512, SMEM_NT>>>(mask);

    softmax_kernel<<<16384, b256>>>();

    out512<<<dim3(4, 16, 8), b512, SMEM_T>>>(out);
}

// round 9
// speedup vs baseline: 1.9747x; 1.1588x over previous
#include <cuda_runtime.h>
#include <cuda_bf16.h>
#include <cstdint>
#include <cstddef>

// ============================================================================
// Attention_5480378270188 — bf16 hi/lo 3-term mma.sync
// k32 chunks, swizzled pad-free smem, 3-stage cp.async ring, 1 barrier/chunk,
// 256-thread CTAs, tile 128x128, warp tile 64x32, 2 CTAs/SM
// ============================================================================

#define DEV_INLINE __device__ __forceinline__
typedef __nv_bfloat16 bf16;

constexpr int NN = 2048;
constexpr int MM = 2048;
constexpr int DD = 1024;
constexpr float NEG = -1000000000.0f;

constexpr size_t QKV_ELEMS = (size_t)8 * 2048 * 1024;
constexpr size_t SCORE_ELEMS = (size_t)8 * 2048 * 2048;

// ---------------- device scratch --------------------------------------------
__device__ bf16 g_xqh[QKV_ELEMS], g_xql[QKV_ELEMS];
__device__ bf16 g_xkh[QKV_ELEMS], g_xkl[QKV_ELEMS];
__device__ bf16 g_xvh[QKV_ELEMS], g_xvl[QKV_ELEMS];
__device__ bf16 g_wqh[1024 * 1024], g_wql[1024 * 1024];
__device__ bf16 g_wkh[1024 * 1024], g_wkl[1024 * 1024];
__device__ bf16 g_wvh[1024 * 1024], g_wvl[1024 * 1024];
__device__ bf16 g_qhi[QKV_ELEMS], g_qlo[QKV_ELEMS];
__device__ bf16 g_khi[QKV_ELEMS], g_klo[QKV_ELEMS];
__device__ bf16 g_vhi[QKV_ELEMS], g_vlo[QKV_ELEMS];
__device__ float g_scores[SCORE_ELEMS];
__device__ bf16 g_whi[SCORE_ELEMS], g_wlo[SCORE_ELEMS];

// ---------------- stage layout (elements), k32 chunks ------------------------
// K-major tiles: 64 B rows (32 bf16), 4 granules of 8 elems, swizzled.
// NT stage:  [Ah 128x32][Al 128x32][Bh 128x32][Bl 128x32] = 16384 elems = 32 KB
// T  stage:  [Ah 128x32][Al 128x32][Bh 32x128][Bl 32x128] = 16384 elems = 32 KB
constexpr int TAE   = 128 * 32;          // 4096 elems per sub-tile
constexpr int STAGE = 4 * TAE;           // 16384 elems
constexpr int SMEM3 = 3 * STAGE * 2;     // 98304 B

// ---------------- PTX helpers -----------------------------------------------
DEV_INLINE uint32_t smem_u32(const void* p) { return (uint32_t)__cvta_generic_to_shared(p); }

DEV_INLINE void cp16(void* dst, const void* src) {
    uint32_t d = smem_u32(dst);
    asm volatile("cp.async.cg.shared.global [%0], [%1], 16;\n"
                 :: "r"(d), "l"(__cvta_generic_to_global(src)) : "memory");
}
#define CP_COMMIT() asm volatile("cp.async.commit_group;\n" ::: "memory")
#define CP_WAIT1()  asm volatile("cp.async.wait_group 1;\n" ::: "memory")
#define CP_WAIT0()  asm volatile("cp.async.wait_group 0;\n" ::: "memory")

DEV_INLINE void ldsm4(uint32_t r[4], const void* p) {
    uint32_t a = smem_u32(p);
    asm volatile("ldmatrix.sync.aligned.m8n8.x4.shared.b16 {%0,%1,%2,%3}, [%4];\n"
                 : "=r"(r[0]), "=r"(r[1]), "=r"(r[2]), "=r"(r[3]) : "r"(a));
}
DEV_INLINE void ldsm4t(uint32_t r[4], const void* p) {
    uint32_t a = smem_u32(p);
    asm volatile("ldmatrix.sync.aligned.m8n8.x4.trans.shared.b16 {%0,%1,%2,%3}, [%4];\n"
                 : "=r"(r[0]), "=r"(r[1]), "=r"(r[2]), "=r"(r[3]) : "r"(a));
}
DEV_INLINE void mma16816(float c[4], const uint32_t a[4], uint32_t b0, uint32_t b1) {
    asm volatile(
        "mma.sync.aligned.m16n8k16.row.col.f32.bf16.bf16.f32 "
        "{%0,%1,%2,%3},{%4,%5,%6,%7},{%8,%9},{%0,%1,%2,%3};\n"
        : "+f"(c[0]), "+f"(c[1]), "+f"(c[2]), "+f"(c[3])
        : "r"(a[0]), "r"(a[1]), "r"(a[2]), "r"(a[3]), "r"(b0), "r"(b1));
}
DEV_INLINE void split1(float v, bf16& h, bf16& l) {
    h = __float2bfloat16(v);
    l = __float2bfloat16(v - __bfloat162float(h));
}

// swizzles (granule index permutation within a row)
DEV_INLINE int swzK(int row, int g) { return g ^ ((row >> 1) & 3); }   // 64B rows
DEV_INLINE int swzT(int row, int g) { return g ^ (row & 7); }          // 256B rows

// ---------------- compute cores: warp tile 64m x 32n, k32 --------------------
DEV_INLINE void compute_nt32(const bf16* st, int wm, int wn, int lane,
                             float (&acc)[4][4][4]) {
    const bf16* sAh = st;
    const bf16* sAl = st + TAE;
    const bf16* sBh = st + 2 * TAE;
    const bf16* sBl = st + 3 * TAE;
#pragma unroll
    for (int kk = 0; kk < 32; kk += 16) {
        uint32_t ah[4][4], al[4][4], b[2][4];
        const int ar = (lane & 15), ag = (kk >> 3) + (lane >> 4);
#pragma unroll
        for (int mt = 0; mt < 4; mt++) {
            int r = wm + mt * 16 + ar;
            int o = r * 32 + swzK(r, ag) * 8;
            ldsm4(ah[mt], sAh + o);
            ldsm4(al[mt], sAl + o);
        }
        const int br0 = (lane >> 4) * 8 + (lane & 7);
        const int bg = (kk >> 3) + ((lane >> 3) & 1);
#pragma unroll
        for (int p = 0; p < 2; p++) {
            int r = wn + p * 16 + br0;
            ldsm4(b[p], sBh + r * 32 + swzK(r, bg) * 8);
        }
#pragma unroll
        for (int mt = 0; mt < 4; mt++)
#pragma unroll
            for (int p = 0; p < 2; p++) {
                mma16816(acc[mt][2 * p],     ah[mt], b[p][0], b[p][1]);
                mma16816(acc[mt][2 * p + 1], ah[mt], b[p][2], b[p][3]);
            }
#pragma unroll
        for (int mt = 0; mt < 4; mt++)
#pragma unroll
            for (int p = 0; p < 2; p++) {
                mma16816(acc[mt][2 * p],     al[mt], b[p][0], b[p][1]);
                mma16816(acc[mt][2 * p + 1], al[mt], b[p][2], b[p][3]);
            }
#pragma unroll
        for (int p = 0; p < 2; p++) {
            int r = wn + p * 16 + br0;
            ldsm4(b[p], sBl + r * 32 + swzK(r, bg) * 8);
        }
#pragma unroll
        for (int mt = 0; mt < 4; mt++)
#pragma unroll
            for (int p = 0; p < 2; p++) {
                mma16816(acc[mt][2 * p],     ah[mt], b[p][0], b[p][1]);
                mma16816(acc[mt][2 * p + 1], ah[mt], b[p][2], b[p][3]);
            }
    }
}

DEV_INLINE void compute_t32(const bf16* st, int wm, int wn, int lane,
                            float (&acc)[4][4][4]) {
    const bf16* sAh = st;
    const bf16* sAl = st + TAE;
    const bf16* sBh = st + 2 * TAE;   // 32 rows x 128 elems (v, d-major)
    const bf16* sBl = st + 3 * TAE;
#pragma unroll
    for (int kk = 0; kk < 32; kk += 16) {
        uint32_t ah[4][4], al[4][4], b[2][4];
        const int ar = (lane & 15), ag = (kk >> 3) + (lane >> 4);
#pragma unroll
        for (int mt = 0; mt < 4; mt++) {
            int r = wm + mt * 16 + ar;
            int o = r * 32 + swzK(r, ag) * 8;
            ldsm4(ah[mt], sAh + o);
            ldsm4(al[mt], sAl + o);
        }
        const int br = kk + ((lane >> 3) & 1) * 8 + (lane & 7);
        const int g0 = (wn >> 3) + (lane >> 4);
#pragma unroll
        for (int p = 0; p < 2; p++) {
            int g = g0 + p * 2;
            ldsm4t(b[p], sBh + br * 128 + swzT(br, g) * 8);
        }
#pragma unroll
        for (int mt = 0; mt < 4; mt++)
#pragma unroll
            for (int p = 0; p < 2; p++) {
                mma16816(acc[mt][2 * p],     ah[mt], b[p][0], b[p][1]);
                mma16816(acc[mt][2 * p + 1], ah[mt], b[p][2], b[p][3]);
            }
#pragma unroll
        for (int mt = 0; mt < 4; mt++)
#pragma unroll
            for (int p = 0; p < 2; p++) {
                mma16816(acc[mt][2 * p],     al[mt], b[p][0], b[p][1]);
                mma16816(acc[mt][2 * p + 1], al[mt], b[p][2], b[p][3]);
            }
#pragma unroll
        for (int p = 0; p < 2; p++) {
            int g = g0 + p * 2;
            ldsm4t(b[p], sBl + br * 128 + swzT(br, g) * 8);
        }
#pragma unroll
        for (int mt = 0; mt < 4; mt++)
#pragma unroll
            for (int p = 0; p < 2; p++) {
                mma16816(acc[mt][2 * p],     ah[mt], b[p][0], b[p][1]);
                mma16816(acc[mt][2 * p + 1], ah[mt], b[p][2], b[p][3]);
            }
    }
}

// ---------------------------------------------------------------------------
// merged projection kernel: grid (8, 128, 3); tile 128x128, warp 2m x 4n
// ---------------------------------------------------------------------------
__global__ __launch_bounds__(256, 2) void proj3(const float* __restrict__ bq,
                                                const float* __restrict__ bk,
                                                const float* __restrict__ bv) {
    extern __shared__ char ds[];
    const int tid = threadIdx.x, lane = tid & 31, warp = tid >> 5;
    const int wm = (warp & 1) * 64, wn = (warp >> 1) * 32;
    const int rowBlk = blockIdx.y * 128, colBlk = blockIdx.x * 128;
    const int z = blockIdx.z;

    const bf16 *Ah, *Al, *Bh, *Bl;
    bf16 *Chi, *Clo;
    const float* bias;
    if (z == 0)      { Ah = g_xqh; Al = g_xql; Bh = g_wqh; Bl = g_wql; Chi = g_qhi; Clo = g_qlo; bias = bq; }
    else if (z == 1) { Ah = g_xkh; Al = g_xkl; Bh = g_wkh; Bl = g_wkl; Chi = g_khi; Clo = g_klo; bias = bk; }
    else             { Ah = g_xvh; Al = g_xvl; Bh = g_wvh; Bl = g_wvl; Chi = g_vhi; Clo = g_vlo; bias = bv; }

    auto issue = [&](int s, int chunk) {
        bf16* st = (bf16*)ds + s * STAGE;
        const int k0 = chunk * 32;
#pragma unroll
        for (int i = 0; i < 2; i++) {
            int u = tid + 256 * i, r = u >> 2, g = u & 3;
            int o = r * 32 + swzK(r, g) * 8;
            size_t ga = (size_t)(rowBlk + r) * 1024 + k0 + g * 8;
            size_t gb = (size_t)(colBlk + r) * 1024 + k0 + g * 8;
            cp16(st + o, Ah + ga);
            cp16(st + TAE + o, Al + ga);
            cp16(st + 2 * TAE + o, Bh + gb);
            cp16(st + 3 * TAE + o, Bl + gb);
        }
    };

    constexpr int C = 32;
    float acc[4][4][4] = {};
    issue(0, 0); CP_COMMIT();
    issue(1, 1); CP_COMMIT();
    for (int it = 0; it < C; it++) {
        if (it + 1 < C) CP_WAIT1(); else CP_WAIT0();
        __syncthreads();
        if (it + 2 < C) { issue((it + 2) % 3, it + 2); CP_COMMIT(); }
        compute_nt32((bf16*)ds + (it % 3) * STAGE, wm, wn, lane, acc);
    }

#pragma unroll
    for (int mt = 0; mt < 4; mt++)
#pragma unroll
        for (int nt = 0; nt < 4; nt++) {
            int r = rowBlk + wm + mt * 16 + (lane >> 2);
            int c = colBlk + wn + nt * 8 + (lane & 3) * 2;
            float b0 = bias[c], b1 = bias[c + 1];
            {
                bf16 h0, l0, h1, l1;
                split1(acc[mt][nt][0] + b0, h0, l0);
                split1(acc[mt][nt][1] + b1, h1, l1);
                *(__nv_bfloat162*)(Chi + (size_t)r * 1024 + c) = __halves2bfloat162(h0, h1);
                *(__nv_bfloat162*)(Clo + (size_t)r * 1024 + c) = __halves2bfloat162(l0, l1);
            }
            {
                bf16 h0, l0, h1, l1;
                split1(acc[mt][nt][2] + b0, h0, l0);
                split1(acc[mt][nt][3] + b1, h1, l1);
                *(__nv_bfloat162*)(Chi + (size_t)(r + 8) * 1024 + c) = __halves2bfloat162(h0, h1);
                *(__nv_bfloat162*)(Clo + (size_t)(r + 8) * 1024 + c) = __halves2bfloat162(l0, l1);
            }
        }
}

// ---------------------------------------------------------------------------
// score kernel: grid (16, 16, 8); z = batch
// ---------------------------------------------------------------------------
__global__ __launch_bounds__(256, 2) void score512(const int* __restrict__ mask) {
    extern __shared__ char ds[];
    const int tid = threadIdx.x, lane = tid & 31, warp = tid >> 5;
    const int wm = (warp & 1) * 64, wn = (warp >> 1) * 32;
    const int rowBlk = blockIdx.y * 128, colBlk = blockIdx.x * 128;
    const int z = blockIdx.z;
    const size_t zoff = (size_t)z * 2048 * 1024;
    const bf16* Ahp = g_qhi + zoff;  const bf16* Alp = g_qlo + zoff;
    const bf16* Bhp = g_khi + zoff;  const bf16* Blp = g_klo + zoff;

    auto issue = [&](int s, int chunk) {
        bf16* st = (bf16*)ds + s * STAGE;
        const int k0 = chunk * 32;
#pragma unroll
        for (int i = 0; i < 2; i++) {
            int u = tid + 256 * i, r = u >> 2, g = u & 3;
            int o = r * 32 + swzK(r, g) * 8;
            size_t ga = (size_t)(rowBlk + r) * 1024 + k0 + g * 8;
            size_t gb = (size_t)(colBlk + r) * 1024 + k0 + g * 8;
            cp16(st + o, Ahp + ga);
            cp16(st + TAE + o, Alp + ga);
            cp16(st + 2 * TAE + o, Bhp + gb);
            cp16(st + 3 * TAE + o, Blp + gb);
        }
    };

    constexpr int C = 32;
    float acc[4][4][4] = {};
    issue(0, 0); CP_COMMIT();
    issue(1, 1); CP_COMMIT();
    for (int it = 0; it < C; it++) {
        if (it + 1 < C) CP_WAIT1(); else CP_WAIT0();
        __syncthreads();
        if (it + 2 < C) { issue((it + 2) % 3, it + 2); CP_COMMIT(); }
        compute_nt32((bf16*)ds + (it % 3) * STAGE, wm, wn, lane, acc);
    }

    float* Sg = g_scores + (size_t)z * NN * MM;
#pragma unroll
    for (int mt = 0; mt < 4; mt++)
#pragma unroll
        for (int nt = 0; nt < 4; nt++) {
            int r = rowBlk + wm + mt * 16 + (lane >> 2);
            int c = colBlk + wn + nt * 8 + (lane & 3) * 2;
            {
                int m0 = mask[(size_t)r * MM + c], m1 = mask[(size_t)r * MM + c + 1];
                float2 v;
                v.x = m0 ? acc[mt][nt][0] : NEG;
                v.y = m1 ? acc[mt][nt][1] : NEG;
                *(float2*)(Sg + (size_t)r * MM + c) = v;
            }
            {
                int rr = r + 8;
                int m0 = mask[(size_t)rr * MM + c], m1 = mask[(size_t)rr * MM + c + 1];
                float2 v;
                v.x = m0 ? acc[mt][nt][2] : NEG;
                v.y = m1 ? acc[mt][nt][3] : NEG;
                *(float2*)(Sg + (size_t)rr * MM + c) = v;
            }
        }
}

// ---------------------------------------------------------------------------
// out kernel: grid (8, 16, 8). O = w·v, B via ldmatrix.trans, K=2048
// ---------------------------------------------------------------------------
__global__ __launch_bounds__(256, 2) void out512(float* __restrict__ O) {
    extern __shared__ char ds[];
    const int tid = threadIdx.x, lane = tid & 31, warp = tid >> 5;
    const int wm = (warp & 1) * 64, wn = (warp >> 1) * 32;
    const int z = blockIdx.z;
    const int rowBlk = blockIdx.y * 128, colBlk = blockIdx.x * 128;
    const bf16* wh = g_whi + (size_t)z * NN * MM;
    const bf16* wl = g_wlo + (size_t)z * NN * MM;
    const bf16* vh = g_vhi + (size_t)z * MM * DD;
    const bf16* vl = g_vlo + (size_t)z * MM * DD;

    auto issue = [&](int s, int chunk) {
        bf16* st = (bf16*)ds + s * STAGE;
        const int k0 = chunk * 32;
#pragma unroll
        for (int i = 0; i < 2; i++) {
            int u = tid + 256 * i;
            {   // A (w): 128 rows x 4 granules
                int r = u >> 2, g = u & 3;
                int o = r * 32 + swzK(r, g) * 8;
                size_t ga = (size_t)(rowBlk + r) * MM + k0 + g * 8;
                cp16(st + o, wh + ga);
                cp16(st + TAE + o, wl + ga);
            }
            {   // B (v): 32 k-rows x 16 granules, 256B rows, swzT
                int r = u >> 4, g = u & 15;
                int o = r * 128 + swzT(r, g) * 8;
                size_t gb = (size_t)(k0 + r) * DD + colBlk + g * 8;
                cp16(st + 2 * TAE + o, vh + gb);
                cp16(st + 3 * TAE + o, vl + gb);
            }
        }
    };

    constexpr int C = 64;
    float acc[4][4][4] = {};
    issue(0, 0); CP_COMMIT();
    issue(1, 1); CP_COMMIT();
    for (int it = 0; it < C; it++) {
        if (it + 1 < C) CP_WAIT1(); else CP_WAIT0();
        __syncthreads();
        if (it + 2 < C) { issue((it + 2) % 3, it + 2); CP_COMMIT(); }
        compute_t32((bf16*)ds + (it % 3) * STAGE, wm, wn, lane, acc);
    }

    float* Og = O + (size_t)z * NN * DD;
#pragma unroll
    for (int mt = 0; mt < 4; mt++)
#pragma unroll
        for (int nt = 0; nt < 4; nt++) {
            int r = rowBlk + wm + mt * 16 + (lane >> 2);
            int c = colBlk + wn + nt * 8 + (lane & 3) * 2;
            float2 v0; v0.x = acc[mt][nt][0]; v0.y = acc[mt][nt][1];
            *(float2*)(Og + (size_t)r * DD + c) = v0;
            float2 v1; v1.x = acc[mt][nt][2]; v1.y = acc[mt][nt][3];
            *(float2*)(Og + (size_t)(r + 8) * DD + c) = v1;
        }
}

// ---------------------------------------------------------------------------
// splits: fp32 [rows,1024] -> hi/lo bf16; merged via grid.y
// ---------------------------------------------------------------------------
__global__ __launch_bounds__(256, 4) void split_in(const float* __restrict__ Xq,
                                                   const float* __restrict__ Xk,
                                                   const float* __restrict__ Xv) {
    const float* X; bf16 *H, *L;
    if (blockIdx.y == 0)      { X = Xq; H = g_xqh; L = g_xql; }
    else if (blockIdx.y == 1) { X = Xk; H = g_xkh; L = g_xkl; }
    else                      { X = Xv; H = g_xvh; L = g_xvl; }
    size_t row = blockIdx.x;
    int t = threadIdx.x;
    float4 v = ((const float4*)(X + row * 1024))[t];
    bf16 h0, l0, h1, l1, h2, l2, h3, l3;
    split1(v.x, h0, l0); split1(v.y, h1, l1);
    split1(v.z, h2, l2); split1(v.w, h3, l3);
    bf16* ph = H + row * 1024 + t * 4;
    bf16* pl = L + row * 1024 + t * 4;
    *(__nv_bfloat162*)(ph)     = __halves2bfloat162(h0, h1);
    *(__nv_bfloat162*)(ph + 2) = __halves2bfloat162(h2, h3);
    *(__nv_bfloat162*)(pl)     = __halves2bfloat162(l0, l1);
    *(__nv_bfloat162*)(pl + 2) = __halves2bfloat162(l2, l3);
}

__global__ __launch_bounds__(256, 4) void split_w(const float* __restrict__ Wq,
                                                  const float* __restrict__ Wk,
                                                  const float* __restrict__ Wv) {
    const float* X; bf16 *H, *L;
    if (blockIdx.y == 0)      { X = Wq; H = g_wqh; L = g_wql; }
    else if (blockIdx.y == 1) { X = Wk; H = g_wkh; L = g_wkl; }
    else                      { X = Wv; H = g_wvh; L = g_wvl; }
    size_t row = blockIdx.x;
    int t = threadIdx.x;
    float4 v = ((const float4*)(X + row * 1024))[t];
    bf16 h0, l0, h1, l1, h2, l2, h3, l3;
    split1(v.x, h0, l0); split1(v.y, h1, l1);
    split1(v.z, h2, l2); split1(v.w, h3, l3);
    bf16* ph = H + row * 1024 + t * 4;
    bf16* pl = L + row * 1024 + t * 4;
    *(__nv_bfloat162*)(ph)     = __halves2bfloat162(h0, h1);
    *(__nv_bfloat162*)(ph + 2) = __halves2bfloat162(h2, h3);
    *(__nv_bfloat162*)(pl)     = __halves2bfloat162(l0, l1);
    *(__nv_bfloat162*)(pl + 2) = __halves2bfloat162(l2, l3);
}

// ---------------------------------------------------------------------------
// softmax: scores row -> weights hi/lo
// ---------------------------------------------------------------------------
__global__ __launch_bounds__(256, 1) void softmax_kernel() {
    const int row = blockIdx.x;
    const int tid = threadIdx.x, lane = tid & 31, warp = tid >> 5;
    const float4* S4 = (const float4*)(g_scores + (size_t)row * MM);
    float4 u0 = S4[tid * 2], u1 = S4[tid * 2 + 1];
    float x[8] = {u0.x, u0.y, u0.z, u0.w, u1.x, u1.y, u1.z, u1.w};

    float mx = x[0];
#pragma unroll
    for (int i = 1; i < 8; i++) mx = fmaxf(mx, x[i]);
#pragma unroll
    for (int o = 16; o; o >>= 1) mx = fmaxf(mx, __shfl_xor_sync(0xffffffffu, mx, o));
    __shared__ float redm[8], reds[8];
    if (lane == 0) redm[warp] = mx;
    __syncthreads();
    mx = redm[0];
#pragma unroll
    for (int i = 1; i < 8; i++) mx = fmaxf(mx, redm[i]);

    float e[8], s = 0.f;
#pragma unroll
    for (int i = 0; i < 8; i++) { e[i] = __expf(x[i] - mx); s += e[i]; }
#pragma unroll
    for (int o = 16; o; o >>= 1) s += __shfl_xor_sync(0xffffffffu, s, o);
    if (lane == 0) reds[warp] = s;
    __syncthreads();
    s = reds[0];
#pragma unroll
    for (int i = 1; i < 8; i++) s += reds[i];
    float inv = 1.0f / s;

    bf16 h[8], l[8];
#pragma unroll
    for (int i = 0; i < 8; i++) split1(e[i] * inv, h[i], l[i]);
    uint4 uh, ul;
    __nv_bfloat162* ph = reinterpret_cast<__nv_bfloat162*>(&uh);
    __nv_bfloat162* pl = reinterpret_cast<__nv_bfloat162*>(&ul);
    ph[0] = __halves2bfloat162(h[0], h[1]); ph[1] = __halves2bfloat162(h[2], h[3]);
    ph[2] = __halves2bfloat162(h[4], h[5]); ph[3] = __halves2bfloat162(h[6], h[7]);
    pl[0] = __halves2bfloat162(l[0], l[1]); pl[1] = __halves2bfloat162(l[2], l[3]);
    pl[2] = __halves2bfloat162(l[4], l[5]); pl[3] = __halves2bfloat162(l[6], l[7]);
    *(uint4*)(g_whi + (size_t)row * MM + tid * 8) = uh;
    *(uint4*)(g_wlo + (size_t)row * MM + tid * 8) = ul;
}

// ---------------------------------------------------------------------------
// Launch
// ---------------------------------------------------------------------------
extern "C" void kernel_launch(void* const* d_in, const int* in_sizes, int n_in,
                              void* d_out, int out_size) {
    (void)in_sizes; (void)n_in; (void)out_size;
    const float* querys = (const float*)d_in[0];
    const float* keys   = (const float*)d_in[1];
    const float* values = (const float*)d_in[2];
    const int*   mask   = (const int*)d_in[3];
    const float* Wq     = (const float*)d_in[4];
    const float* bq     = (const float*)d_in[5];
    const float* Wk     = (const float*)d_in[6];
    const float* bk     = (const float*)d_in[7];
    const float* Wv     = (const float*)d_in[8];
    const float* bv     = (const float*)d_in[9];
    float* out = (float*)d_out;

    static bool attr_done = false;
    if (!attr_done) {
        cudaFuncSetAttribute(proj3, cudaFuncAttributeMaxDynamicSharedMemorySize, SMEM3);
        cudaFuncSetAttribute(score512, cudaFuncAttributeMaxDynamicSharedMemorySize, SMEM3);
        cudaFuncSetAttribute(out512, cudaFuncAttributeMaxDynamicSharedMemorySize, SMEM3);
        attr_done = true;
    }

    dim3 b256(256);
    split_in<<<dim3(16384, 3), b256>>>(querys, keys, values);
    split_w<<<dim3(1024, 3), b256>>>(Wq, Wk, Wv);

    proj3<<<dim3(8, 128, 3), b256, SMEM3>>>(bq, bk, bv);

    score512<<<dim3(16, 16, 8), b256, SMEM3>>>(mask);

    softmax_kernel<<<16384, b256>>>();

    out512<<<dim3(8, 16, 8), b256, SMEM3>>>(out);
}